// round 4
// baseline (speedup 1.0000x reference)
#include <cuda_runtime.h>
#include <cstdint>

// ---------------------------------------------------------------------------
// MLP over graph edges, factored:
//   h1 = relu(drug[i] @ W1a^T + dis[j] @ W1b^T + b1)
//      = relu(A[i] + B[j])          with A, B precomputed per node
//   h2 = relu(h1 @ W2^T + b2)       (TF32 tensor-core GEMM)
//   out = h2 @ W3^T + b3            (register epilogue + quad shuffle reduce)
//
// R3: 32 edges per warp (two m16 subtiles per B-fragment load) to halve the
// dominant L1 component (W2 SMEM re-reads): 4KB -> 3KB L1 bytes per edge.
// ---------------------------------------------------------------------------

#define IN_UNITS   128
#define H1_DIM     128
#define H2_DIM     64
#define N_DRUG_MAX 10000
#define N_DIS_MAX  5000
#define N_EDGE_MAX 2000000

#define WARP_E     32                 // edges per warp
#define NWARP      8
#define TILE_E     (WARP_E * NWARP)   // 256 edges per CTA tile
#define H1_STRIDE  132   // pad: conflict-free A-fragment LDS, 16B-aligned rows
#define W2_STRIDE  132

__device__ __align__(16) float g_A[N_DRUG_MAX * H1_DIM];
__device__ __align__(16) float g_B[N_DIS_MAX * H1_DIM];
__device__ int g_ei[2 * N_EDGE_MAX];   // normalized int32 indices

__device__ __forceinline__ float tf32r(float x) {
    uint32_t u;
    asm("cvt.rna.tf32.f32 %0, %1;" : "=r"(u) : "f"(x));
    return __uint_as_float(u);
}

__device__ __forceinline__ void mma_m16n8k8_tf32(float acc[4],
        uint32_t a0, uint32_t a1, uint32_t a2, uint32_t a3,
        uint32_t b0, uint32_t b1) {
    asm volatile(
        "mma.sync.aligned.m16n8k8.row.col.f32.tf32.tf32.f32 "
        "{%0,%1,%2,%3}, {%4,%5,%6,%7}, {%8,%9}, {%0,%1,%2,%3};\n"
        : "+f"(acc[0]), "+f"(acc[1]), "+f"(acc[2]), "+f"(acc[3])
        : "r"(a0), "r"(a1), "r"(a2), "r"(a3), "r"(b0), "r"(b1));
}

// ---------------------------------------------------------------------------
// Index normalization (int64 vs int32 ambiguity in harness). With int64 data
// every value < 5000 -> hi 32 bits of each word are 0; with int32 data the hi
// word is the next index (nonzero w.p. 4999/5000). 64 words checked.
// ---------------------------------------------------------------------------
__global__ void normalize_idx(const void* __restrict__ raw, int n_total) {
    const unsigned long long* r64 = (const unsigned long long*)raw;
    const int* r32 = (const int*)raw;

    bool is64 = true;
    #pragma unroll
    for (int k = 0; k < 64; k++)
        if (r64[k] >> 32) { is64 = false; break; }

    int t = blockIdx.x * blockDim.x + threadIdx.x;
    if (t < n_total)
        g_ei[t] = is64 ? (int)((const long long*)raw)[t] : r32[t];
}

// ---------------------------------------------------------------------------
// Precompute: A[row] = drug_feat[row] @ W1[:, 0:128]^T
//             B[row] = dis_feat[row]  @ W1[:, 128:256]^T + b1
// ---------------------------------------------------------------------------
#define RPB 4

__global__ void precompute_A(const float* __restrict__ feat,
                             const float* __restrict__ W1, int nrows) {
    int row0 = blockIdx.x * RPB;
    int c = threadIdx.x;
    __shared__ float sf[RPB][IN_UNITS];
    for (int r = 0; r < RPB; r++) {
        int row = row0 + r;
        sf[r][c] = (row < nrows) ? feat[row * IN_UNITS + c] : 0.f;
    }
    __syncthreads();
    float acc[RPB] = {0.f, 0.f, 0.f, 0.f};
    const float4* w = (const float4*)(W1 + c * (2 * IN_UNITS));
#pragma unroll
    for (int k = 0; k < IN_UNITS / 4; k++) {
        float4 ww = w[k];
#pragma unroll
        for (int r = 0; r < RPB; r++) {
            float4 f = *(const float4*)&sf[r][k * 4];
            acc[r] += f.x * ww.x + f.y * ww.y + f.z * ww.z + f.w * ww.w;
        }
    }
    for (int r = 0; r < RPB; r++) {
        int row = row0 + r;
        if (row < nrows) g_A[row * H1_DIM + c] = acc[r];
    }
}

__global__ void precompute_B(const float* __restrict__ feat,
                             const float* __restrict__ W1,
                             const float* __restrict__ b1, int nrows) {
    int row0 = blockIdx.x * RPB;
    int c = threadIdx.x;
    __shared__ float sf[RPB][IN_UNITS];
    for (int r = 0; r < RPB; r++) {
        int row = row0 + r;
        sf[r][c] = (row < nrows) ? feat[row * IN_UNITS + c] : 0.f;
    }
    __syncthreads();
    float b1c = b1[c];
    float acc[RPB] = {b1c, b1c, b1c, b1c};
    const float4* w = (const float4*)(W1 + c * (2 * IN_UNITS) + IN_UNITS);
#pragma unroll
    for (int k = 0; k < IN_UNITS / 4; k++) {
        float4 ww = w[k];
#pragma unroll
        for (int r = 0; r < RPB; r++) {
            float4 f = *(const float4*)&sf[r][k * 4];
            acc[r] += f.x * ww.x + f.y * ww.y + f.z * ww.z + f.w * ww.w;
        }
    }
    for (int r = 0; r < RPB; r++) {
        int row = row0 + r;
        if (row < nrows) g_B[row * H1_DIM + c] = acc[r];
    }
}

// ---------------------------------------------------------------------------
// Main fused kernel: per 256-edge CTA tile, each warp owns 32 edges:
//   phase A: gather relu(A[i]+B[j]) -> warp-private SMEM (tf32-rounded)
//   phase B: two m16 x n64 x k128 TF32 MMA chains sharing every B fragment
//   phase C: bias + relu + W3 dot in registers, quad shuffle reduce, store
// No block-level syncs in the tile loop.
// ---------------------------------------------------------------------------
__global__ __launch_bounds__(256, 1)
void edge_mlp_kernel(const float* __restrict__ W2,
                     const float* __restrict__ b2,
                     const float* __restrict__ W3,
                     const float* __restrict__ b3,
                     float* __restrict__ out,
                     int E, int ntiles) {
    extern __shared__ float smem[];
    float* H1  = smem;                         // TILE_E * H1_STRIDE
    float* W2s = H1 + TILE_E * H1_STRIDE;      // H2_DIM * W2_STRIDE
    float* b2s = W2s + H2_DIM * W2_STRIDE;     // H2_DIM
    float* w3s = b2s + H2_DIM;                 // H2_DIM

    int tid = threadIdx.x;

    // Stage W2 (tf32-rounded), b2, W3 once per CTA.
    for (int t = tid; t < H2_DIM * H1_DIM; t += blockDim.x) {
        int n = t >> 7, k = t & 127;
        W2s[n * W2_STRIDE + k] = tf32r(W2[t]);
    }
    if (tid < H2_DIM) { b2s[tid] = b2[tid]; w3s[tid] = W3[tid]; }
    __syncthreads();
    float b3v = __ldg(b3);

    int warp = tid >> 5;
    int lane = tid & 31;
    int g  = lane >> 2;   // mma groupID
    int tg = lane & 3;    // mma thread-in-group
    float* Hrow = H1 + warp * WARP_E * H1_STRIDE;

    for (int tile = blockIdx.x; tile < ntiles; tile += gridDim.x) {
        int ebase = tile * TILE_E + warp * WARP_E;

        // Per-lane indices for 32 edges (drug + dis), coalesced.
        int e = ebase + lane;
        int idx_d = 0, idx_s = 0;
        if (e < E) {
            idx_d = g_ei[e];
            idx_s = g_ei[E + e];
        }

        // ---- gather: h1 = tf32(relu(A[i] + B[j])) into warp-private SMEM ----
#pragma unroll 4
        for (int q = 0; q < WARP_E; q++) {
            int i = __shfl_sync(0xffffffffu, idx_d, q);
            int j = __shfl_sync(0xffffffffu, idx_s, q);
            float4 a = *(const float4*)(g_A + i * H1_DIM + lane * 4);
            float4 b = *(const float4*)(g_B + j * H1_DIM + lane * 4);
            float4 v;
            v.x = tf32r(fmaxf(a.x + b.x, 0.f));
            v.y = tf32r(fmaxf(a.y + b.y, 0.f));
            v.z = tf32r(fmaxf(a.z + b.z, 0.f));
            v.w = tf32r(fmaxf(a.w + b.w, 0.f));
            *(float4*)(Hrow + q * H1_STRIDE + lane * 4) = v;
        }
        __syncwarp();

        // ---- layer 2: 2 x (16 edges) x 64 ch x 128 k TF32 MMA ----
        float acc[2][8][4];
#pragma unroll
        for (int m = 0; m < 2; m++)
#pragma unroll
            for (int n = 0; n < 8; n++)
                acc[m][n][0] = acc[m][n][1] = acc[m][n][2] = acc[m][n][3] = 0.f;

#pragma unroll
        for (int s = 0; s < 16; s++) {
            int k0 = s * 8;
            uint32_t a[2][4];
#pragma unroll
            for (int m = 0; m < 2; m++) {
                const float* Hm = Hrow + m * 16 * H1_STRIDE;
                a[m][0] = __float_as_uint(Hm[g * H1_STRIDE + k0 + tg]);
                a[m][1] = __float_as_uint(Hm[(g + 8) * H1_STRIDE + k0 + tg]);
                a[m][2] = __float_as_uint(Hm[g * H1_STRIDE + k0 + tg + 4]);
                a[m][3] = __float_as_uint(Hm[(g + 8) * H1_STRIDE + k0 + tg + 4]);
            }
#pragma unroll
            for (int n = 0; n < 8; n++) {
                uint32_t b0 = __float_as_uint(W2s[(n * 8 + g) * W2_STRIDE + k0 + tg]);
                uint32_t b1 = __float_as_uint(W2s[(n * 8 + g) * W2_STRIDE + k0 + tg + 4]);
                mma_m16n8k8_tf32(acc[0][n], a[0][0], a[0][1], a[0][2], a[0][3], b0, b1);
                mma_m16n8k8_tf32(acc[1][n], a[1][0], a[1][1], a[1][2], a[1][3], b0, b1);
            }
        }

        // ---- epilogue: relu(h2 + b2) . W3 + b3, reduced across the quad ----
#pragma unroll
        for (int m = 0; m < 2; m++) {
            float o0 = 0.f, o1 = 0.f;
#pragma unroll
            for (int n = 0; n < 8; n++) {
                int c0 = n * 8 + 2 * tg;
                float bb0 = b2s[c0], bb1 = b2s[c0 + 1];
                float w0 = w3s[c0],  w1 = w3s[c0 + 1];
                o0 += fmaxf(acc[m][n][0] + bb0, 0.f) * w0
                    + fmaxf(acc[m][n][1] + bb1, 0.f) * w1;
                o1 += fmaxf(acc[m][n][2] + bb0, 0.f) * w0
                    + fmaxf(acc[m][n][3] + bb1, 0.f) * w1;
            }
            o0 += __shfl_xor_sync(0xffffffffu, o0, 1);
            o0 += __shfl_xor_sync(0xffffffffu, o0, 2);
            o1 += __shfl_xor_sync(0xffffffffu, o1, 1);
            o1 += __shfl_xor_sync(0xffffffffu, o1, 2);
            if (tg == 0) {
                int e0 = ebase + m * 16 + g;
                int e1 = e0 + 8;
                if (e0 < E) out[e0] = o0 + b3v;
                if (e1 < E) out[e1] = o1 + b3v;
            }
        }
        __syncwarp();   // next tile's gather rewrites rows this warp just read
    }
}

// ---------------------------------------------------------------------------
// Launch
// ---------------------------------------------------------------------------
extern "C" void kernel_launch(void* const* d_in, const int* in_sizes, int n_in,
                              void* d_out, int out_size) {
    const float* drug = (const float*)d_in[0];
    const float* dis  = (const float*)d_in[1];
    const void*  eraw = d_in[2];
    const float* W1   = (const float*)d_in[3];
    const float* b1   = (const float*)d_in[4];
    const float* W2   = (const float*)d_in[5];
    const float* b2   = (const float*)d_in[6];
    const float* W3   = (const float*)d_in[7];
    const float* b3   = (const float*)d_in[8];
    float* out = (float*)d_out;

    int n_drug  = in_sizes[0] / IN_UNITS;
    int n_dis   = in_sizes[1] / IN_UNITS;
    int n_total = in_sizes[2];       // 2*E elements regardless of dtype
    int E       = n_total / 2;
    int ntiles  = (E + TILE_E - 1) / TILE_E;

    normalize_idx<<<(n_total + 255) / 256, 256>>>(eraw, n_total);
    precompute_A<<<(n_drug + RPB - 1) / RPB, IN_UNITS>>>(drug, W1, n_drug);
    precompute_B<<<(n_dis + RPB - 1) / RPB, IN_UNITS>>>(dis, W1, b1, n_dis);

    constexpr int smem_bytes =
        (TILE_E * H1_STRIDE + H2_DIM * W2_STRIDE + 2 * H2_DIM) * 4;
    cudaFuncSetAttribute(edge_mlp_kernel,
                         cudaFuncAttributeMaxDynamicSharedMemorySize,
                         smem_bytes);

    int grid = 148;  // persistent, 1 CTA/SM (169KB smem)
    if (grid > ntiles) grid = ntiles;
    edge_mlp_kernel<<<grid, 256, smem_bytes>>>(W2, b2, W3, b3, out, E, ntiles);
}

// round 5
// speedup vs baseline: 1.1390x; 1.1390x over previous
#include <cuda_runtime.h>
#include <cstdint>

// ---------------------------------------------------------------------------
// MLP over graph edges, factored:
//   h1 = relu(drug[i] @ W1a^T + dis[j] @ W1b^T + b1)
//      = relu(A[i] + B[j])          with A, B precomputed per node
//   h2 = relu(h1 @ W2^T + b2)       (TF32 tensor-core GEMM)
//   out = h2 @ W3^T + b3            (register epilogue + quad shuffle reduce)
//
// R4: keep 32 edges/warp W2 reuse (3KB L1 bytes/edge) but restore latency
// coverage: XOR-swizzled, pad-free SMEM (H1 rows 512B, W2 32KB) lets a single
// 384-thread CTA (12 warps) fit in 224.5KB -> 12 warps/SM vs R3's 8.
// ---------------------------------------------------------------------------

#define IN_UNITS   128
#define H1_DIM     128
#define H2_DIM     64
#define N_DRUG_MAX 10000
#define N_DIS_MAX  5000
#define N_EDGE_MAX 2000000

#define WARP_E     32                 // edges per warp
#define NWARP      12
#define NTHREADS   (NWARP * 32)
#define TILE_E     (WARP_E * NWARP)   // 384 edges per CTA tile

__device__ __align__(16) float g_A[N_DRUG_MAX * H1_DIM];
__device__ __align__(16) float g_B[N_DIS_MAX * H1_DIM];
__device__ int g_ei[2 * N_EDGE_MAX];   // normalized int32 indices

__device__ __forceinline__ float tf32r(float x) {
    uint32_t u;
    asm("cvt.rna.tf32.f32 %0, %1;" : "=r"(u) : "f"(x));
    return __uint_as_float(u);
}

__device__ __forceinline__ void mma_m16n8k8_tf32(float acc[4],
        uint32_t a0, uint32_t a1, uint32_t a2, uint32_t a3,
        uint32_t b0, uint32_t b1) {
    asm volatile(
        "mma.sync.aligned.m16n8k8.row.col.f32.tf32.tf32.f32 "
        "{%0,%1,%2,%3}, {%4,%5,%6,%7}, {%8,%9}, {%0,%1,%2,%3};\n"
        : "+f"(acc[0]), "+f"(acc[1]), "+f"(acc[2]), "+f"(acc[3])
        : "r"(a0), "r"(a1), "r"(a2), "r"(a3), "r"(b0), "r"(b1));
}

// ---------------------------------------------------------------------------
// Index normalization (int64 vs int32 ambiguity in harness). With int64 data
// every value < 5000 -> hi 32 bits of each word are 0; with int32 data the hi
// word is the next index (nonzero w.p. 4999/5000). 64 words checked.
// ---------------------------------------------------------------------------
__global__ void normalize_idx(const void* __restrict__ raw, int n_total) {
    const unsigned long long* r64 = (const unsigned long long*)raw;
    const int* r32 = (const int*)raw;

    bool is64 = true;
    #pragma unroll
    for (int k = 0; k < 64; k++)
        if (r64[k] >> 32) { is64 = false; break; }

    int t = blockIdx.x * blockDim.x + threadIdx.x;
    if (t < n_total)
        g_ei[t] = is64 ? (int)((const long long*)raw)[t] : r32[t];
}

// ---------------------------------------------------------------------------
// Precompute: A[row] = drug_feat[row] @ W1[:, 0:128]^T
//             B[row] = dis_feat[row]  @ W1[:, 128:256]^T + b1
// ---------------------------------------------------------------------------
#define RPB 4

__global__ void precompute_A(const float* __restrict__ feat,
                             const float* __restrict__ W1, int nrows) {
    int row0 = blockIdx.x * RPB;
    int c = threadIdx.x;
    __shared__ float sf[RPB][IN_UNITS];
    for (int r = 0; r < RPB; r++) {
        int row = row0 + r;
        sf[r][c] = (row < nrows) ? feat[row * IN_UNITS + c] : 0.f;
    }
    __syncthreads();
    float acc[RPB] = {0.f, 0.f, 0.f, 0.f};
    const float4* w = (const float4*)(W1 + c * (2 * IN_UNITS));
#pragma unroll
    for (int k = 0; k < IN_UNITS / 4; k++) {
        float4 ww = w[k];
#pragma unroll
        for (int r = 0; r < RPB; r++) {
            float4 f = *(const float4*)&sf[r][k * 4];
            acc[r] += f.x * ww.x + f.y * ww.y + f.z * ww.z + f.w * ww.w;
        }
    }
    for (int r = 0; r < RPB; r++) {
        int row = row0 + r;
        if (row < nrows) g_A[row * H1_DIM + c] = acc[r];
    }
}

__global__ void precompute_B(const float* __restrict__ feat,
                             const float* __restrict__ W1,
                             const float* __restrict__ b1, int nrows) {
    int row0 = blockIdx.x * RPB;
    int c = threadIdx.x;
    __shared__ float sf[RPB][IN_UNITS];
    for (int r = 0; r < RPB; r++) {
        int row = row0 + r;
        sf[r][c] = (row < nrows) ? feat[row * IN_UNITS + c] : 0.f;
    }
    __syncthreads();
    float b1c = b1[c];
    float acc[RPB] = {b1c, b1c, b1c, b1c};
    const float4* w = (const float4*)(W1 + c * (2 * IN_UNITS) + IN_UNITS);
#pragma unroll
    for (int k = 0; k < IN_UNITS / 4; k++) {
        float4 ww = w[k];
#pragma unroll
        for (int r = 0; r < RPB; r++) {
            float4 f = *(const float4*)&sf[r][k * 4];
            acc[r] += f.x * ww.x + f.y * ww.y + f.z * ww.z + f.w * ww.w;
        }
    }
    for (int r = 0; r < RPB; r++) {
        int row = row0 + r;
        if (row < nrows) g_B[row * H1_DIM + c] = acc[r];
    }
}

// ---------------------------------------------------------------------------
// Main fused kernel. SMEM layout (XOR-swizzled, no padding):
//   H1:  NWARP * 32 rows * 128 floats (row r: float4 group c4 stored at
//        c4 ^ (r&7)) -> conflict-free gather stores AND fragment loads.
//   W2s: 64 rows * 128 floats, same swizzle per row.
// Per warp: 32 edges, two m16n64k128 MMA chains sharing every B fragment.
// ---------------------------------------------------------------------------
__global__ __launch_bounds__(NTHREADS, 1)
void edge_mlp_kernel(const float* __restrict__ W2,
                     const float* __restrict__ b2,
                     const float* __restrict__ W3,
                     const float* __restrict__ b3,
                     float* __restrict__ out,
                     int E, int ntiles) {
    extern __shared__ float smem[];
    float* H1  = smem;                            // TILE_E * 128
    float* W2s = H1 + TILE_E * H1_DIM;            // 64 * 128
    float* b2s = W2s + H2_DIM * H1_DIM;           // 64
    float* w3s = b2s + H2_DIM;                    // 64

    int tid = threadIdx.x;

    // Stage W2 (tf32-rounded, swizzled), b2, W3 once per CTA.
    for (int t = tid; t < H2_DIM * H1_DIM; t += NTHREADS) {
        int n = t >> 7, k = t & 127;
        int phys = n * 128 + (((k >> 2) ^ (n & 7)) << 2) + (k & 3);
        W2s[phys] = tf32r(W2[t]);
    }
    if (tid < H2_DIM) { b2s[tid] = b2[tid]; w3s[tid] = W3[tid]; }
    __syncthreads();
    float b3v = __ldg(b3);

    int warp = tid >> 5;
    int lane = tid & 31;
    int g  = lane >> 2;   // mma groupID
    int tg = lane & 3;    // mma thread-in-group
    float* Hrow = H1 + warp * WARP_E * H1_DIM;

    for (int tile = blockIdx.x; tile < ntiles; tile += gridDim.x) {
        int ebase = tile * TILE_E + warp * WARP_E;

        // Per-lane indices for 32 edges (drug + dis), coalesced.
        int e = ebase + lane;
        int idx_d = 0, idx_s = 0;
        if (e < E) {
            idx_d = g_ei[e];
            idx_s = g_ei[E + e];
        }

        // ---- gather: h1 = tf32(relu(A[i] + B[j])) -> swizzled SMEM ----
#pragma unroll 4
        for (int q = 0; q < WARP_E; q++) {
            int i = __shfl_sync(0xffffffffu, idx_d, q);
            int j = __shfl_sync(0xffffffffu, idx_s, q);
            float4 a = *(const float4*)(g_A + i * H1_DIM + lane * 4);
            float4 b = *(const float4*)(g_B + j * H1_DIM + lane * 4);
            float4 v;
            v.x = tf32r(fmaxf(a.x + b.x, 0.f));
            v.y = tf32r(fmaxf(a.y + b.y, 0.f));
            v.z = tf32r(fmaxf(a.z + b.z, 0.f));
            v.w = tf32r(fmaxf(a.w + b.w, 0.f));
            *(float4*)(Hrow + q * H1_DIM + ((lane ^ (q & 7)) << 2)) = v;
        }
        __syncwarp();

        // ---- layer 2: 2 x (16 edges) x 64 ch x 128 k TF32 MMA ----
        float acc[2][8][4];
#pragma unroll
        for (int m = 0; m < 2; m++)
#pragma unroll
            for (int n = 0; n < 8; n++)
                acc[m][n][0] = acc[m][n][1] = acc[m][n][2] = acc[m][n][3] = 0.f;

#pragma unroll
        for (int s = 0; s < 16; s++) {
            // swizzled intra-row offsets for col pairs (k0+tg, k0+4+tg), rows with r&7==g
            int p0 = ((((2 * s)     ^ g) << 2) + tg);
            int p1 = ((((2 * s + 1) ^ g) << 2) + tg);
            uint32_t a[2][4];
#pragma unroll
            for (int m = 0; m < 2; m++) {
                const float* Hm = Hrow + m * 16 * H1_DIM;
                a[m][0] = __float_as_uint(Hm[g * H1_DIM + p0]);
                a[m][1] = __float_as_uint(Hm[(g + 8) * H1_DIM + p0]);
                a[m][2] = __float_as_uint(Hm[g * H1_DIM + p1]);
                a[m][3] = __float_as_uint(Hm[(g + 8) * H1_DIM + p1]);
            }
#pragma unroll
            for (int n = 0; n < 8; n++) {
                const float* Wn = W2s + (n * 8 + g) * H1_DIM;
                uint32_t b0 = __float_as_uint(Wn[p0]);
                uint32_t b1 = __float_as_uint(Wn[p1]);
                mma_m16n8k8_tf32(acc[0][n], a[0][0], a[0][1], a[0][2], a[0][3], b0, b1);
                mma_m16n8k8_tf32(acc[1][n], a[1][0], a[1][1], a[1][2], a[1][3], b0, b1);
            }
        }

        // ---- epilogue: relu(h2 + b2) . W3 + b3, reduced across the quad ----
#pragma unroll
        for (int m = 0; m < 2; m++) {
            float o0 = 0.f, o1 = 0.f;
#pragma unroll
            for (int n = 0; n < 8; n++) {
                int c0 = n * 8 + 2 * tg;
                float bb0 = b2s[c0], bb1 = b2s[c0 + 1];
                float w0 = w3s[c0],  w1 = w3s[c0 + 1];
                o0 += fmaxf(acc[m][n][0] + bb0, 0.f) * w0
                    + fmaxf(acc[m][n][1] + bb1, 0.f) * w1;
                o1 += fmaxf(acc[m][n][2] + bb0, 0.f) * w0
                    + fmaxf(acc[m][n][3] + bb1, 0.f) * w1;
            }
            o0 += __shfl_xor_sync(0xffffffffu, o0, 1);
            o0 += __shfl_xor_sync(0xffffffffu, o0, 2);
            o1 += __shfl_xor_sync(0xffffffffu, o1, 1);
            o1 += __shfl_xor_sync(0xffffffffu, o1, 2);
            if (tg == 0) {
                int e0 = ebase + m * 16 + g;
                int e1 = e0 + 8;
                if (e0 < E) out[e0] = o0 + b3v;
                if (e1 < E) out[e1] = o1 + b3v;
            }
        }
        __syncwarp();   // next tile's gather rewrites rows this warp just read
    }
}

// ---------------------------------------------------------------------------
// Launch
// ---------------------------------------------------------------------------
extern "C" void kernel_launch(void* const* d_in, const int* in_sizes, int n_in,
                              void* d_out, int out_size) {
    const float* drug = (const float*)d_in[0];
    const float* dis  = (const float*)d_in[1];
    const void*  eraw = d_in[2];
    const float* W1   = (const float*)d_in[3];
    const float* b1   = (const float*)d_in[4];
    const float* W2   = (const float*)d_in[5];
    const float* b2   = (const float*)d_in[6];
    const float* W3   = (const float*)d_in[7];
    const float* b3   = (const float*)d_in[8];
    float* out = (float*)d_out;

    int n_drug  = in_sizes[0] / IN_UNITS;
    int n_dis   = in_sizes[1] / IN_UNITS;
    int n_total = in_sizes[2];       // 2*E elements regardless of dtype
    int E       = n_total / 2;
    int ntiles  = (E + TILE_E - 1) / TILE_E;

    normalize_idx<<<(n_total + 255) / 256, 256>>>(eraw, n_total);
    precompute_A<<<(n_drug + RPB - 1) / RPB, IN_UNITS>>>(drug, W1, n_drug);
    precompute_B<<<(n_dis + RPB - 1) / RPB, IN_UNITS>>>(dis, W1, b1, n_dis);

    constexpr int smem_bytes =
        (TILE_E * H1_DIM + H2_DIM * H1_DIM + 2 * H2_DIM) * 4;  // ~224.5 KB
    cudaFuncSetAttribute(edge_mlp_kernel,
                         cudaFuncAttributeMaxDynamicSharedMemorySize,
                         smem_bytes);

    int grid = 148;  // persistent, 1 CTA/SM
    if (grid > ntiles) grid = ntiles;
    edge_mlp_kernel<<<grid, NTHREADS, smem_bytes>>>(W2, b2, W3, b3, out, E, ntiles);
}

// round 6
// speedup vs baseline: 1.5689x; 1.3775x over previous
#include <cuda_runtime.h>
#include <cuda_fp16.h>
#include <cstdint>

// ---------------------------------------------------------------------------
// MLP over graph edges, factored:
//   h1 = relu(drug[i] @ W1a^T + dis[j] @ W1b^T + b1) = relu(A[i] + B[j])
//   h2 = relu(h1 @ W2^T + b2)       (FP16 tensor-core GEMM, fp32 accum)
//   out = h2 @ W3^T + b3            (register epilogue + quad shuffle reduce)
//
// R5: fp16 MMA path (same 11-bit mantissa as tf32) -> ldmatrix fragment
// loads, 2 KB L1 bytes/edge, 80.5 KB SMEM/CTA -> 2 CTAs/SM (16 warps).
// ---------------------------------------------------------------------------

#define IN_UNITS   128
#define H1_DIM     128
#define H2_DIM     64
#define N_DRUG_MAX 10000
#define N_DIS_MAX  5000
#define N_EDGE_MAX 2000000

#define WARP_E     32                 // edges per warp
#define NWARP      8
#define NTHREADS   (NWARP * 32)
#define TILE_E     (WARP_E * NWARP)   // 256 edges per CTA tile

__device__ __align__(16) float g_A[N_DRUG_MAX * H1_DIM];
__device__ __align__(16) float g_B[N_DIS_MAX * H1_DIM];
__device__ int g_ei[2 * N_EDGE_MAX];   // normalized int32 indices

__device__ __forceinline__ uint32_t smem_u32(const void* p) {
    return (uint32_t)__cvta_generic_to_shared(p);
}

__device__ __forceinline__ void ldsm_x4(uint32_t& r0, uint32_t& r1,
                                        uint32_t& r2, uint32_t& r3,
                                        uint32_t addr) {
    asm volatile("ldmatrix.sync.aligned.m8n8.x4.shared.b16 {%0,%1,%2,%3}, [%4];"
                 : "=r"(r0), "=r"(r1), "=r"(r2), "=r"(r3) : "r"(addr));
}
__device__ __forceinline__ void ldsm_x2(uint32_t& r0, uint32_t& r1,
                                        uint32_t addr) {
    asm volatile("ldmatrix.sync.aligned.m8n8.x2.shared.b16 {%0,%1}, [%2];"
                 : "=r"(r0), "=r"(r1) : "r"(addr));
}
__device__ __forceinline__ void mma_fp16(float acc[4],
        uint32_t a0, uint32_t a1, uint32_t a2, uint32_t a3,
        uint32_t b0, uint32_t b1) {
    asm volatile(
        "mma.sync.aligned.m16n8k16.row.col.f32.f16.f16.f32 "
        "{%0,%1,%2,%3}, {%4,%5,%6,%7}, {%8,%9}, {%0,%1,%2,%3};\n"
        : "+f"(acc[0]), "+f"(acc[1]), "+f"(acc[2]), "+f"(acc[3])
        : "r"(a0), "r"(a1), "r"(a2), "r"(a3), "r"(b0), "r"(b1));
}

// ---------------------------------------------------------------------------
// Index normalization (int64 vs int32 ambiguity in harness). With int64 data
// every value < 5000 -> hi 32 bits of each word are 0; with int32 data the hi
// word is the next index (nonzero w.p. 4999/5000). 64 words checked.
// ---------------------------------------------------------------------------
__global__ void normalize_idx(const void* __restrict__ raw, int n_total) {
    const unsigned long long* r64 = (const unsigned long long*)raw;
    const int* r32 = (const int*)raw;

    bool is64 = true;
    #pragma unroll
    for (int k = 0; k < 64; k++)
        if (r64[k] >> 32) { is64 = false; break; }

    int t = blockIdx.x * blockDim.x + threadIdx.x;
    if (t < n_total)
        g_ei[t] = is64 ? (int)((const long long*)raw)[t] : r32[t];
}

// ---------------------------------------------------------------------------
// Precompute: A[row] = drug_feat[row] @ W1[:, 0:128]^T
//             B[row] = dis_feat[row]  @ W1[:, 128:256]^T + b1
// ---------------------------------------------------------------------------
#define RPB 4

__global__ void precompute_A(const float* __restrict__ feat,
                             const float* __restrict__ W1, int nrows) {
    int row0 = blockIdx.x * RPB;
    int c = threadIdx.x;
    __shared__ float sf[RPB][IN_UNITS];
    for (int r = 0; r < RPB; r++) {
        int row = row0 + r;
        sf[r][c] = (row < nrows) ? feat[row * IN_UNITS + c] : 0.f;
    }
    __syncthreads();
    float acc[RPB] = {0.f, 0.f, 0.f, 0.f};
    const float4* w = (const float4*)(W1 + c * (2 * IN_UNITS));
#pragma unroll
    for (int k = 0; k < IN_UNITS / 4; k++) {
        float4 ww = w[k];
#pragma unroll
        for (int r = 0; r < RPB; r++) {
            float4 f = *(const float4*)&sf[r][k * 4];
            acc[r] += f.x * ww.x + f.y * ww.y + f.z * ww.z + f.w * ww.w;
        }
    }
    for (int r = 0; r < RPB; r++) {
        int row = row0 + r;
        if (row < nrows) g_A[row * H1_DIM + c] = acc[r];
    }
}

__global__ void precompute_B(const float* __restrict__ feat,
                             const float* __restrict__ W1,
                             const float* __restrict__ b1, int nrows) {
    int row0 = blockIdx.x * RPB;
    int c = threadIdx.x;
    __shared__ float sf[RPB][IN_UNITS];
    for (int r = 0; r < RPB; r++) {
        int row = row0 + r;
        sf[r][c] = (row < nrows) ? feat[row * IN_UNITS + c] : 0.f;
    }
    __syncthreads();
    float b1c = b1[c];
    float acc[RPB] = {b1c, b1c, b1c, b1c};
    const float4* w = (const float4*)(W1 + c * (2 * IN_UNITS) + IN_UNITS);
#pragma unroll
    for (int k = 0; k < IN_UNITS / 4; k++) {
        float4 ww = w[k];
#pragma unroll
        for (int r = 0; r < RPB; r++) {
            float4 f = *(const float4*)&sf[r][k * 4];
            acc[r] += f.x * ww.x + f.y * ww.y + f.z * ww.z + f.w * ww.w;
        }
    }
    for (int r = 0; r < RPB; r++) {
        int row = row0 + r;
        if (row < nrows) g_B[row * H1_DIM + c] = acc[r];
    }
}

// ---------------------------------------------------------------------------
// Main fused kernel. SMEM (fp16, XOR-swizzled at 16B granularity):
//   H1h:  TILE_E rows x 128 halves (256B/row, 16 chunks; phys chunk = c^(r&7))
//   W2h:  64 rows x 128 halves, same swizzle
// Per warp: 32 edges; fragments via ldmatrix; 2x(m16 n64 k128) HMMA chains.
// ---------------------------------------------------------------------------
struct alignas(8) h2x2 { __half2 a, b; };

__global__ __launch_bounds__(NTHREADS, 2)
void edge_mlp_kernel(const float* __restrict__ W2,
                     const float* __restrict__ b2,
                     const float* __restrict__ W3,
                     const float* __restrict__ b3,
                     float* __restrict__ out,
                     int E, int ntiles) {
    extern __shared__ __half smemh[];
    __half* H1h = smemh;                          // TILE_E * 128 halves
    __half* W2h = H1h + TILE_E * H1_DIM;          // 64 * 128 halves
    float*  b2s = (float*)(W2h + H2_DIM * H1_DIM);
    float*  w3s = b2s + H2_DIM;

    int tid = threadIdx.x;

    // Stage W2 (fp16, swizzled), b2, W3 once per CTA.
    for (int t = tid; t < H2_DIM * H1_DIM; t += NTHREADS) {
        int n = t >> 7, k = t & 127;
        int phys = n * H1_DIM + (((k >> 3) ^ (n & 7)) << 3) + (k & 7);
        W2h[phys] = __float2half_rn(W2[t]);
    }
    if (tid < H2_DIM) { b2s[tid] = b2[tid]; w3s[tid] = W3[tid]; }
    __syncthreads();
    float b3v = __ldg(b3);

    int warp = tid >> 5;
    int lane = tid & 31;
    int g  = lane >> 2;   // mma groupID
    int tg = lane & 3;    // mma thread-in-group
    __half* Hw = H1h + warp * WARP_E * H1_DIM;
    uint32_t hw_u32 = smem_u32(Hw);
    uint32_t w2_u32 = smem_u32(W2h);

    // ldmatrix address components (constant across tiles/s except chunk)
    int ar = lane & 15;           // A-frag row within m16 (mats 0/1 rows, 2/3 same)
    int ac_hi = lane >> 4;        // 0: k-low chunk, 1: k-high chunk
    int bn = lane & 7;            // B-frag row within n8
    int bc_hi = (lane >> 3) & 1;  // 0: k-low, 1: k-high

    for (int tile = blockIdx.x; tile < ntiles; tile += gridDim.x) {
        int ebase = tile * TILE_E + warp * WARP_E;

        // Per-lane indices for 32 edges (drug + dis), coalesced.
        int e = ebase + lane;
        int idx_d = 0, idx_s = 0;
        if (e < E) {
            idx_d = g_ei[e];
            idx_s = g_ei[E + e];
        }

        // ---- gather: h1 = fp16(relu(A[i] + B[j])) -> swizzled SMEM ----
        // lane covers halves [lane*4, lane*4+4): chunk c = lane>>1, off (lane&1)*4
#pragma unroll 4
        for (int q = 0; q < WARP_E; q++) {
            int i = __shfl_sync(0xffffffffu, idx_d, q);
            int j = __shfl_sync(0xffffffffu, idx_s, q);
            float4 a = *(const float4*)(g_A + i * H1_DIM + lane * 4);
            float4 b = *(const float4*)(g_B + j * H1_DIM + lane * 4);
            h2x2 v;
            v.a = __floats2half2_rn(fmaxf(a.x + b.x, 0.f), fmaxf(a.y + b.y, 0.f));
            v.b = __floats2half2_rn(fmaxf(a.z + b.z, 0.f), fmaxf(a.w + b.w, 0.f));
            __half* dst = Hw + q * H1_DIM
                        + ((((lane >> 1) ^ (q & 7)) << 3) + ((lane & 1) << 2));
            *(h2x2*)dst = v;
        }
        __syncwarp();

        // ---- layer 2: 2 x (m16 x n64 x k128) fp16 MMA, fp32 accum ----
        float acc[2][8][4];
#pragma unroll
        for (int m = 0; m < 2; m++)
#pragma unroll
            for (int n = 0; n < 8; n++)
                acc[m][n][0] = acc[m][n][1] = acc[m][n][2] = acc[m][n][3] = 0.f;

#pragma unroll
        for (int s = 0; s < 8; s++) {           // k16 steps
            int ca = 2 * s + ac_hi;             // A chunk for this lane
            uint32_t A0[4], A1[4];
            {
                int r0 = ar;                     // m-tile 0 rows 0..15
                uint32_t ad0 = hw_u32 + ((r0 * H1_DIM + ((ca ^ (r0 & 7)) << 3)) << 1);
                ldsm_x4(A0[0], A0[1], A0[2], A0[3], ad0);
                int r1 = 16 + ar;                // m-tile 1 rows 16..31
                uint32_t ad1 = hw_u32 + ((r1 * H1_DIM + ((ca ^ (r1 & 7)) << 3)) << 1);
                ldsm_x4(A1[0], A1[1], A1[2], A1[3], ad1);
            }
            int cb = 2 * s + bc_hi;
#pragma unroll
            for (int nt = 0; nt < 8; nt++) {
                int nr = nt * 8 + bn;
                uint32_t bad = w2_u32 + ((nr * H1_DIM + ((cb ^ (nr & 7)) << 3)) << 1);
                uint32_t b0, b1;
                ldsm_x2(b0, b1, bad);
                mma_fp16(acc[0][nt], A0[0], A0[1], A0[2], A0[3], b0, b1);
                mma_fp16(acc[1][nt], A1[0], A1[1], A1[2], A1[3], b0, b1);
            }
        }

        // ---- epilogue: relu(h2 + b2) . W3 + b3, reduced across the quad ----
#pragma unroll
        for (int m = 0; m < 2; m++) {
            float o0 = 0.f, o1 = 0.f;
#pragma unroll
            for (int n = 0; n < 8; n++) {
                int c0 = n * 8 + 2 * tg;
                float bb0 = b2s[c0], bb1 = b2s[c0 + 1];
                float w0 = w3s[c0],  w1 = w3s[c0 + 1];
                o0 += fmaxf(acc[m][n][0] + bb0, 0.f) * w0
                    + fmaxf(acc[m][n][1] + bb1, 0.f) * w1;
                o1 += fmaxf(acc[m][n][2] + bb0, 0.f) * w0
                    + fmaxf(acc[m][n][3] + bb1, 0.f) * w1;
            }
            o0 += __shfl_xor_sync(0xffffffffu, o0, 1);
            o0 += __shfl_xor_sync(0xffffffffu, o0, 2);
            o1 += __shfl_xor_sync(0xffffffffu, o1, 1);
            o1 += __shfl_xor_sync(0xffffffffu, o1, 2);
            if (tg == 0) {
                int e0 = ebase + m * 16 + g;
                int e1 = e0 + 8;
                if (e0 < E) out[e0] = o0 + b3v;
                if (e1 < E) out[e1] = o1 + b3v;
            }
        }
        __syncwarp();   // next tile's gather rewrites rows this warp just read
    }
}

// ---------------------------------------------------------------------------
// Launch
// ---------------------------------------------------------------------------
extern "C" void kernel_launch(void* const* d_in, const int* in_sizes, int n_in,
                              void* d_out, int out_size) {
    const float* drug = (const float*)d_in[0];
    const float* dis  = (const float*)d_in[1];
    const void*  eraw = d_in[2];
    const float* W1   = (const float*)d_in[3];
    const float* b1   = (const float*)d_in[4];
    const float* W2   = (const float*)d_in[5];
    const float* b2   = (const float*)d_in[6];
    const float* W3   = (const float*)d_in[7];
    const float* b3   = (const float*)d_in[8];
    float* out = (float*)d_out;

    int n_drug  = in_sizes[0] / IN_UNITS;
    int n_dis   = in_sizes[1] / IN_UNITS;
    int n_total = in_sizes[2];       // 2*E elements regardless of dtype
    int E       = n_total / 2;
    int ntiles  = (E + TILE_E - 1) / TILE_E;

    normalize_idx<<<(n_total + 255) / 256, 256>>>(eraw, n_total);
    precompute_A<<<(n_drug + RPB - 1) / RPB, IN_UNITS>>>(drug, W1, n_drug);
    precompute_B<<<(n_dis + RPB - 1) / RPB, IN_UNITS>>>(dis, W1, b1, n_dis);

    constexpr int smem_bytes =
        (TILE_E * H1_DIM + H2_DIM * H1_DIM) * 2 + 2 * H2_DIM * 4;  // 82.4 KB
    cudaFuncSetAttribute(edge_mlp_kernel,
                         cudaFuncAttributeMaxDynamicSharedMemorySize,
                         smem_bytes);

    int grid = 296;  // persistent, 2 CTAs/SM
    if (grid > ntiles) grid = ntiles;
    edge_mlp_kernel<<<grid, NTHREADS, smem_bytes>>>(W2, b2, W3, b3, out, E, ntiles);
}

// round 7
// speedup vs baseline: 1.7616x; 1.1228x over previous
#include <cuda_runtime.h>
#include <cuda_fp16.h>
#include <cstdint>

// ---------------------------------------------------------------------------
// MLP over graph edges, factored:
//   h1 = relu(drug[i] @ W1a^T + dis[j] @ W1b^T + b1) = relu(A[i] + B[j])
//   h2 = relu(h1 @ W2^T + b2)       (FP16 tensor-core GEMM, fp32 accum)
//   out = h2 @ W3^T + b3            (register epilogue + quad shuffle reduce)
//
// R6: node tables A/B stored fp16 -> gather L1/L2 bytes halved
// (2 -> 1.5 KB L1 per edge); h1 sum via half2 ALU.
// ---------------------------------------------------------------------------

#define IN_UNITS   128
#define H1_DIM     128
#define H2_DIM     64
#define N_DRUG_MAX 10000
#define N_DIS_MAX  5000
#define N_EDGE_MAX 2000000

#define WARP_E     32                 // edges per warp
#define NWARP      8
#define NTHREADS   (NWARP * 32)
#define TILE_E     (WARP_E * NWARP)   // 256 edges per CTA tile

__device__ __align__(16) __half g_Ah[N_DRUG_MAX * H1_DIM];
__device__ __align__(16) __half g_Bh[N_DIS_MAX * H1_DIM];
__device__ int g_ei[2 * N_EDGE_MAX];   // normalized int32 indices

__device__ __forceinline__ uint32_t smem_u32(const void* p) {
    return (uint32_t)__cvta_generic_to_shared(p);
}

__device__ __forceinline__ void ldsm_x4(uint32_t& r0, uint32_t& r1,
                                        uint32_t& r2, uint32_t& r3,
                                        uint32_t addr) {
    asm volatile("ldmatrix.sync.aligned.m8n8.x4.shared.b16 {%0,%1,%2,%3}, [%4];"
                 : "=r"(r0), "=r"(r1), "=r"(r2), "=r"(r3) : "r"(addr));
}
__device__ __forceinline__ void ldsm_x2(uint32_t& r0, uint32_t& r1,
                                        uint32_t addr) {
    asm volatile("ldmatrix.sync.aligned.m8n8.x2.shared.b16 {%0,%1}, [%2];"
                 : "=r"(r0), "=r"(r1) : "r"(addr));
}
__device__ __forceinline__ void mma_fp16(float acc[4],
        uint32_t a0, uint32_t a1, uint32_t a2, uint32_t a3,
        uint32_t b0, uint32_t b1) {
    asm volatile(
        "mma.sync.aligned.m16n8k16.row.col.f32.f16.f16.f32 "
        "{%0,%1,%2,%3}, {%4,%5,%6,%7}, {%8,%9}, {%0,%1,%2,%3};\n"
        : "+f"(acc[0]), "+f"(acc[1]), "+f"(acc[2]), "+f"(acc[3])
        : "r"(a0), "r"(a1), "r"(a2), "r"(a3), "r"(b0), "r"(b1));
}

// ---------------------------------------------------------------------------
// Index normalization (int64 vs int32 ambiguity in harness). With int64 data
// every value < 5000 -> hi 32 bits of each word are 0; with int32 data the hi
// word is the next index (nonzero w.p. 4999/5000). 64 words checked.
// ---------------------------------------------------------------------------
__global__ void normalize_idx(const void* __restrict__ raw, int n_total) {
    const unsigned long long* r64 = (const unsigned long long*)raw;
    const int* r32 = (const int*)raw;

    bool is64 = true;
    #pragma unroll
    for (int k = 0; k < 64; k++)
        if (r64[k] >> 32) { is64 = false; break; }

    int t = blockIdx.x * blockDim.x + threadIdx.x;
    if (t < n_total)
        g_ei[t] = is64 ? (int)((const long long*)raw)[t] : r32[t];
}

// ---------------------------------------------------------------------------
// Precompute (fp32 math, fp16 store):
//   A[row] = drug_feat[row] @ W1[:, 0:128]^T
//   B[row] = dis_feat[row]  @ W1[:, 128:256]^T + b1
// ---------------------------------------------------------------------------
#define RPB 4

__global__ void precompute_A(const float* __restrict__ feat,
                             const float* __restrict__ W1, int nrows) {
    int row0 = blockIdx.x * RPB;
    int c = threadIdx.x;
    __shared__ float sf[RPB][IN_UNITS];
    for (int r = 0; r < RPB; r++) {
        int row = row0 + r;
        sf[r][c] = (row < nrows) ? feat[row * IN_UNITS + c] : 0.f;
    }
    __syncthreads();
    float acc[RPB] = {0.f, 0.f, 0.f, 0.f};
    const float4* w = (const float4*)(W1 + c * (2 * IN_UNITS));
#pragma unroll
    for (int k = 0; k < IN_UNITS / 4; k++) {
        float4 ww = w[k];
#pragma unroll
        for (int r = 0; r < RPB; r++) {
            float4 f = *(const float4*)&sf[r][k * 4];
            acc[r] += f.x * ww.x + f.y * ww.y + f.z * ww.z + f.w * ww.w;
        }
    }
    for (int r = 0; r < RPB; r++) {
        int row = row0 + r;
        if (row < nrows) g_Ah[row * H1_DIM + c] = __float2half_rn(acc[r]);
    }
}

__global__ void precompute_B(const float* __restrict__ feat,
                             const float* __restrict__ W1,
                             const float* __restrict__ b1, int nrows) {
    int row0 = blockIdx.x * RPB;
    int c = threadIdx.x;
    __shared__ float sf[RPB][IN_UNITS];
    for (int r = 0; r < RPB; r++) {
        int row = row0 + r;
        sf[r][c] = (row < nrows) ? feat[row * IN_UNITS + c] : 0.f;
    }
    __syncthreads();
    float b1c = b1[c];
    float acc[RPB] = {b1c, b1c, b1c, b1c};
    const float4* w = (const float4*)(W1 + c * (2 * IN_UNITS) + IN_UNITS);
#pragma unroll
    for (int k = 0; k < IN_UNITS / 4; k++) {
        float4 ww = w[k];
#pragma unroll
        for (int r = 0; r < RPB; r++) {
            float4 f = *(const float4*)&sf[r][k * 4];
            acc[r] += f.x * ww.x + f.y * ww.y + f.z * ww.z + f.w * ww.w;
        }
    }
    for (int r = 0; r < RPB; r++) {
        int row = row0 + r;
        if (row < nrows) g_Bh[row * H1_DIM + c] = __float2half_rn(acc[r]);
    }
}

// ---------------------------------------------------------------------------
// Main fused kernel. SMEM (fp16, XOR-swizzled at 16B granularity):
//   H1h:  TILE_E rows x 128 halves (256B/row, 16 chunks; phys chunk = c^(r&7))
//   W2h:  64 rows x 128 halves, same swizzle
// Per warp: 32 edges; fragments via ldmatrix; 2x(m16 n64 k128) HMMA chains.
// ---------------------------------------------------------------------------
struct alignas(8) h2x2 { __half2 a, b; };

__global__ __launch_bounds__(NTHREADS, 2)
void edge_mlp_kernel(const float* __restrict__ W2,
                     const float* __restrict__ b2,
                     const float* __restrict__ W3,
                     const float* __restrict__ b3,
                     float* __restrict__ out,
                     int E, int ntiles) {
    extern __shared__ __half smemh[];
    __half* H1h = smemh;                          // TILE_E * 128 halves
    __half* W2h = H1h + TILE_E * H1_DIM;          // 64 * 128 halves
    float*  b2s = (float*)(W2h + H2_DIM * H1_DIM);
    float*  w3s = b2s + H2_DIM;

    int tid = threadIdx.x;

    // Stage W2 (fp16, swizzled), b2, W3 once per CTA.
    for (int t = tid; t < H2_DIM * H1_DIM; t += NTHREADS) {
        int n = t >> 7, k = t & 127;
        int phys = n * H1_DIM + (((k >> 3) ^ (n & 7)) << 3) + (k & 7);
        W2h[phys] = __float2half_rn(W2[t]);
    }
    if (tid < H2_DIM) { b2s[tid] = b2[tid]; w3s[tid] = W3[tid]; }
    __syncthreads();
    float b3v = __ldg(b3);

    int warp = tid >> 5;
    int lane = tid & 31;
    int g  = lane >> 2;   // mma groupID
    int tg = lane & 3;    // mma thread-in-group
    __half* Hw = H1h + warp * WARP_E * H1_DIM;
    uint32_t hw_u32 = smem_u32(Hw);
    uint32_t w2_u32 = smem_u32(W2h);

    // ldmatrix address components
    int ar = lane & 15;           // A-frag row within m16
    int ac_hi = lane >> 4;        // 0: k-low chunk, 1: k-high chunk
    int bn = lane & 7;            // B-frag row within n8
    int bc_hi = (lane >> 3) & 1;  // 0: k-low, 1: k-high

    const __half2 h2zero = __floats2half2_rn(0.f, 0.f);

    for (int tile = blockIdx.x; tile < ntiles; tile += gridDim.x) {
        int ebase = tile * TILE_E + warp * WARP_E;

        // Per-lane indices for 32 edges (drug + dis), coalesced.
        int e = ebase + lane;
        int idx_d = 0, idx_s = 0;
        if (e < E) {
            idx_d = g_ei[e];
            idx_s = g_ei[E + e];
        }

        // ---- gather: h1 = relu(A[i] + B[j]) in fp16 -> swizzled SMEM ----
        // lane covers halves [lane*4, lane*4+4): chunk c = lane>>1, off (lane&1)*4
#pragma unroll 4
        for (int q = 0; q < WARP_E; q++) {
            int i = __shfl_sync(0xffffffffu, idx_d, q);
            int j = __shfl_sync(0xffffffffu, idx_s, q);
            h2x2 a = *(const h2x2*)(g_Ah + i * H1_DIM + lane * 4);
            h2x2 b = *(const h2x2*)(g_Bh + j * H1_DIM + lane * 4);
            h2x2 v;
            v.a = __hmax2(__hadd2(a.a, b.a), h2zero);
            v.b = __hmax2(__hadd2(a.b, b.b), h2zero);
            __half* dst = Hw + q * H1_DIM
                        + ((((lane >> 1) ^ (q & 7)) << 3) + ((lane & 1) << 2));
            *(h2x2*)dst = v;
        }
        __syncwarp();

        // ---- layer 2: 2 x (m16 x n64 x k128) fp16 MMA, fp32 accum ----
        float acc[2][8][4];
#pragma unroll
        for (int m = 0; m < 2; m++)
#pragma unroll
            for (int n = 0; n < 8; n++)
                acc[m][n][0] = acc[m][n][1] = acc[m][n][2] = acc[m][n][3] = 0.f;

#pragma unroll
        for (int s = 0; s < 8; s++) {           // k16 steps
            int ca = 2 * s + ac_hi;             // A chunk for this lane
            uint32_t A0[4], A1[4];
            {
                int r0 = ar;                     // m-tile 0 rows 0..15
                uint32_t ad0 = hw_u32 + ((r0 * H1_DIM + ((ca ^ (r0 & 7)) << 3)) << 1);
                ldsm_x4(A0[0], A0[1], A0[2], A0[3], ad0);
                int r1 = 16 + ar;                // m-tile 1 rows 16..31
                uint32_t ad1 = hw_u32 + ((r1 * H1_DIM + ((ca ^ (r1 & 7)) << 3)) << 1);
                ldsm_x4(A1[0], A1[1], A1[2], A1[3], ad1);
            }
            int cb = 2 * s + bc_hi;
#pragma unroll
            for (int nt = 0; nt < 8; nt++) {
                int nr = nt * 8 + bn;
                uint32_t bad = w2_u32 + ((nr * H1_DIM + ((cb ^ (nr & 7)) << 3)) << 1);
                uint32_t b0, b1;
                ldsm_x2(b0, b1, bad);
                mma_fp16(acc[0][nt], A0[0], A0[1], A0[2], A0[3], b0, b1);
                mma_fp16(acc[1][nt], A1[0], A1[1], A1[2], A1[3], b0, b1);
            }
        }

        // ---- epilogue: relu(h2 + b2) . W3 + b3, reduced across the quad ----
#pragma unroll
        for (int m = 0; m < 2; m++) {
            float o0 = 0.f, o1 = 0.f;
#pragma unroll
            for (int n = 0; n < 8; n++) {
                int c0 = n * 8 + 2 * tg;
                float bb0 = b2s[c0], bb1 = b2s[c0 + 1];
                float w0 = w3s[c0],  w1 = w3s[c0 + 1];
                o0 += fmaxf(acc[m][n][0] + bb0, 0.f) * w0
                    + fmaxf(acc[m][n][1] + bb1, 0.f) * w1;
                o1 += fmaxf(acc[m][n][2] + bb0, 0.f) * w0
                    + fmaxf(acc[m][n][3] + bb1, 0.f) * w1;
            }
            o0 += __shfl_xor_sync(0xffffffffu, o0, 1);
            o0 += __shfl_xor_sync(0xffffffffu, o0, 2);
            o1 += __shfl_xor_sync(0xffffffffu, o1, 1);
            o1 += __shfl_xor_sync(0xffffffffu, o1, 2);
            if (tg == 0) {
                int e0 = ebase + m * 16 + g;
                int e1 = e0 + 8;
                if (e0 < E) out[e0] = o0 + b3v;
                if (e1 < E) out[e1] = o1 + b3v;
            }
        }
        __syncwarp();   // next tile's gather rewrites rows this warp just read
    }
}

// ---------------------------------------------------------------------------
// Launch
// ---------------------------------------------------------------------------
extern "C" void kernel_launch(void* const* d_in, const int* in_sizes, int n_in,
                              void* d_out, int out_size) {
    const float* drug = (const float*)d_in[0];
    const float* dis  = (const float*)d_in[1];
    const void*  eraw = d_in[2];
    const float* W1   = (const float*)d_in[3];
    const float* b1   = (const float*)d_in[4];
    const float* W2   = (const float*)d_in[5];
    const float* b2   = (const float*)d_in[6];
    const float* W3   = (const float*)d_in[7];
    const float* b3   = (const float*)d_in[8];
    float* out = (float*)d_out;

    int n_drug  = in_sizes[0] / IN_UNITS;
    int n_dis   = in_sizes[1] / IN_UNITS;
    int n_total = in_sizes[2];       // 2*E elements regardless of dtype
    int E       = n_total / 2;
    int ntiles  = (E + TILE_E - 1) / TILE_E;

    normalize_idx<<<(n_total + 255) / 256, 256>>>(eraw, n_total);
    precompute_A<<<(n_drug + RPB - 1) / RPB, IN_UNITS>>>(drug, W1, n_drug);
    precompute_B<<<(n_dis + RPB - 1) / RPB, IN_UNITS>>>(dis, W1, b1, n_dis);

    constexpr int smem_bytes =
        (TILE_E * H1_DIM + H2_DIM * H1_DIM) * 2 + 2 * H2_DIM * 4;  // 82.4 KB
    cudaFuncSetAttribute(edge_mlp_kernel,
                         cudaFuncAttributeMaxDynamicSharedMemorySize,
                         smem_bytes);

    int grid = 296;  // persistent, 2 CTAs/SM
    if (grid > ntiles) grid = ntiles;
    edge_mlp_kernel<<<grid, NTHREADS, smem_bytes>>>(W2, b2, W3, b3, out, E, ntiles);
}

// round 9
// speedup vs baseline: 1.9731x; 1.1200x over previous
#include <cuda_runtime.h>
#include <cuda_fp16.h>
#include <cstdint>

// ---------------------------------------------------------------------------
// MLP over graph edges, factored:
//   h1 = relu(drug[i] @ W1a^T + dis[j] @ W1b^T + b1) = relu(A[i] + B[j])
//   h2 = relu(h1 @ W2^T + b2)       (FP16 tensor-core GEMM, fp32 accum)
//   out = h2 @ W3^T + b3            (register epilogue + quad shuffle reduce)
//
// R8: R7's instruction diet with the gather-store addressing bug fixed:
// row offsets are ADDs (base only 256-aligned); XOR confined to the pure
// chunk field (bits 4..7).
// ---------------------------------------------------------------------------

#define IN_UNITS   128
#define H1_DIM     128
#define H2_DIM     64
#define N_DRUG_MAX 10000
#define N_DIS_MAX  5000
#define N_EDGE_MAX 2000000

#define WARP_E     32                 // edges per warp
#define NWARP      8
#define NTHREADS   (NWARP * 32)
#define TILE_E     (WARP_E * NWARP)   // 256 edges per CTA tile

__device__ __align__(16) __half g_Ah[N_DRUG_MAX * H1_DIM];
__device__ __align__(16) __half g_Bh[N_DIS_MAX * H1_DIM];
__device__ int g_ei[2 * N_EDGE_MAX];   // normalized int32 indices

__device__ __forceinline__ uint32_t smem_u32(const void* p) {
    return (uint32_t)__cvta_generic_to_shared(p);
}

__device__ __forceinline__ void ldsm_x4(uint32_t& r0, uint32_t& r1,
                                        uint32_t& r2, uint32_t& r3,
                                        uint32_t addr) {
    asm volatile("ldmatrix.sync.aligned.m8n8.x4.shared.b16 {%0,%1,%2,%3}, [%4];"
                 : "=r"(r0), "=r"(r1), "=r"(r2), "=r"(r3) : "r"(addr));
}
__device__ __forceinline__ void ldsm_x2(uint32_t& r0, uint32_t& r1,
                                        uint32_t addr) {
    asm volatile("ldmatrix.sync.aligned.m8n8.x2.shared.b16 {%0,%1}, [%2];"
                 : "=r"(r0), "=r"(r1) : "r"(addr));
}
__device__ __forceinline__ void sts128(uint32_t addr, uint32_t r0, uint32_t r1,
                                       uint32_t r2, uint32_t r3) {
    asm volatile("st.shared.v4.b32 [%0], {%1,%2,%3,%4};"
                 :: "r"(addr), "r"(r0), "r"(r1), "r"(r2), "r"(r3) : "memory");
}
__device__ __forceinline__ void mma_fp16(float acc[4],
        uint32_t a0, uint32_t a1, uint32_t a2, uint32_t a3,
        uint32_t b0, uint32_t b1) {
    asm volatile(
        "mma.sync.aligned.m16n8k16.row.col.f32.f16.f16.f32 "
        "{%0,%1,%2,%3}, {%4,%5,%6,%7}, {%8,%9}, {%0,%1,%2,%3};\n"
        : "+f"(acc[0]), "+f"(acc[1]), "+f"(acc[2]), "+f"(acc[3])
        : "r"(a0), "r"(a1), "r"(a2), "r"(a3), "r"(b0), "r"(b1));
}

// ---------------------------------------------------------------------------
// Index normalization (int64 vs int32 ambiguity in harness).
// ---------------------------------------------------------------------------
__global__ void normalize_idx(const void* __restrict__ raw, int n_total) {
    const unsigned long long* r64 = (const unsigned long long*)raw;
    const int* r32 = (const int*)raw;

    bool is64 = true;
    #pragma unroll
    for (int k = 0; k < 64; k++)
        if (r64[k] >> 32) { is64 = false; break; }

    int t = blockIdx.x * blockDim.x + threadIdx.x;
    if (t < n_total)
        g_ei[t] = is64 ? (int)((const long long*)raw)[t] : r32[t];
}

// ---------------------------------------------------------------------------
// Precompute (fp32 math, fp16 store):
//   A[row] = drug_feat[row] @ W1[:, 0:128]^T
//   B[row] = dis_feat[row]  @ W1[:, 128:256]^T + b1
// ---------------------------------------------------------------------------
#define RPB 4

__global__ void precompute_A(const float* __restrict__ feat,
                             const float* __restrict__ W1, int nrows) {
    int row0 = blockIdx.x * RPB;
    int c = threadIdx.x;
    __shared__ float sf[RPB][IN_UNITS];
    for (int r = 0; r < RPB; r++) {
        int row = row0 + r;
        sf[r][c] = (row < nrows) ? feat[row * IN_UNITS + c] : 0.f;
    }
    __syncthreads();
    float acc[RPB] = {0.f, 0.f, 0.f, 0.f};
    const float4* w = (const float4*)(W1 + c * (2 * IN_UNITS));
#pragma unroll
    for (int k = 0; k < IN_UNITS / 4; k++) {
        float4 ww = w[k];
#pragma unroll
        for (int r = 0; r < RPB; r++) {
            float4 f = *(const float4*)&sf[r][k * 4];
            acc[r] += f.x * ww.x + f.y * ww.y + f.z * ww.z + f.w * ww.w;
        }
    }
    for (int r = 0; r < RPB; r++) {
        int row = row0 + r;
        if (row < nrows) g_Ah[row * H1_DIM + c] = __float2half_rn(acc[r]);
    }
}

__global__ void precompute_B(const float* __restrict__ feat,
                             const float* __restrict__ W1,
                             const float* __restrict__ b1, int nrows) {
    int row0 = blockIdx.x * RPB;
    int c = threadIdx.x;
    __shared__ float sf[RPB][IN_UNITS];
    for (int r = 0; r < RPB; r++) {
        int row = row0 + r;
        sf[r][c] = (row < nrows) ? feat[row * IN_UNITS + c] : 0.f;
    }
    __syncthreads();
    float b1c = b1[c];
    float acc[RPB] = {b1c, b1c, b1c, b1c};
    const float4* w = (const float4*)(W1 + c * (2 * IN_UNITS) + IN_UNITS);
#pragma unroll
    for (int k = 0; k < IN_UNITS / 4; k++) {
        float4 ww = w[k];
#pragma unroll
        for (int r = 0; r < RPB; r++) {
            float4 f = *(const float4*)&sf[r][k * 4];
            acc[r] += f.x * ww.x + f.y * ww.y + f.z * ww.z + f.w * ww.w;
        }
    }
    for (int r = 0; r < RPB; r++) {
        int row = row0 + r;
        if (row < nrows) g_Bh[row * H1_DIM + c] = __float2half_rn(acc[r]);
    }
}

// ---------------------------------------------------------------------------
// Main fused kernel. SMEM (fp16, XOR-swizzled, 16B chunk granularity):
//   H1h:  TILE_E rows x 256B (16 chunks/row; phys chunk = c ^ (row&7))
//   W2h:  64 rows x 256B, same swizzle
// Row offsets always ADD; XOR only inside the chunk field (bits 4..7).
// ---------------------------------------------------------------------------
__global__ __launch_bounds__(NTHREADS, 2)
void edge_mlp_kernel(const float* __restrict__ W2,
                     const float* __restrict__ b2,
                     const float* __restrict__ W3,
                     const float* __restrict__ b3,
                     float* __restrict__ out,
                     int E, int ntiles) {
    extern __shared__ char smraw[];
    // 256B-align the working base so the chunk field (bits 4..7) is pure.
    uint32_t s0 = smem_u32(smraw);
    uint32_t padb = ((s0 + 255u) & ~255u) - s0;
    char* smbase = smraw + padb;
    __half* H1h = (__half*)smbase;                 // TILE_E * 128 halves
    __half* W2h = H1h + TILE_E * H1_DIM;           // 64 * 128 halves
    float*  b2s = (float*)(W2h + H2_DIM * H1_DIM); // 64
    float*  w3s = b2s + H2_DIM;                    // 64

    int tid = threadIdx.x;

    // Stage W2 (fp16, swizzled), b2, W3 once per CTA.
    for (int t = tid; t < H2_DIM * H1_DIM; t += NTHREADS) {
        int n = t >> 7, k = t & 127;
        int phys = n * H1_DIM + (((k >> 3) ^ (n & 7)) << 3) + (k & 7);
        W2h[phys] = __float2half_rn(W2[t]);
    }
    if (tid < H2_DIM) { b2s[tid] = b2[tid]; w3s[tid] = W3[tid]; }
    __syncthreads();
    float b3v = __ldg(b3);

    int warp = tid >> 5;
    int lane = tid & 31;
    int g  = lane >> 2;   // mma groupID
    int tg = lane & 3;    // mma thread-in-group
    uint32_t hw_u32 = smem_u32(H1h) + warp * (WARP_E * 256);  // 8KB/warp
    uint32_t w2_u32 = smem_u32(W2h);

    // ---- address constants ----
    // Gather store: lane sl covers 16B chunk sl of edge row qq = q2 + hh.
    //   dst = hw + qq*256 + ((sl ^ (qq&7))<<4)
    //       = (hw + hh*256) + q2*256 + (((sl^hh)<<4) ^ ((q2&7)<<4))
    int sl = lane & 15;
    int hh = lane >> 4;
    uint32_t KSrow = hw_u32 + ((uint32_t)hh << 8);
    uint32_t KC    = (uint32_t)((sl ^ hh) << 4);
    // A-fragment ldmatrix: addr(m,s) = (KA0 + m*4096) ^ (s<<5)
    int ar = lane & 15;
    int ac_hi = lane >> 4;
    uint32_t KA0 = hw_u32 + (ar << 8) + ((((ar & 7) ^ ac_hi)) << 4);
    // B-fragment ldmatrix: addr(nt,s) = (KB0 + nt*2048) ^ (s<<5)
    int bn = lane & 7;
    int bc_hi = (lane >> 3) & 1;
    uint32_t KB0 = w2_u32 + (bn << 8) + (((bn ^ bc_hi)) << 4);

    const __half2 h2zero = __floats2half2_rn(0.f, 0.f);
    const char* gAc = (const char*)g_Ah;
    const char* gBc = (const char*)g_Bh;

    for (int tile = blockIdx.x; tile < ntiles; tile += gridDim.x) {
        int ebase = tile * TILE_E + warp * WARP_E;

        // Per-lane indices for 32 edges (drug + dis), coalesced.
        int e = ebase + lane;
        int idx_d = 0, idx_s = 0;
        if (e < E) {
            idx_d = g_ei[e];
            idx_s = g_ei[E + e];
        }

        // ---- gather: 2 edges/iteration, 16B per lane ----
#pragma unroll
        for (int q2 = 0; q2 < WARP_E; q2 += 2) {
            int qq = q2 + hh;
            int i = __shfl_sync(0xffffffffu, idx_d, qq);
            int j = __shfl_sync(0xffffffffu, idx_s, qq);
            uint4 av = *(const uint4*)(gAc + (((size_t)(uint32_t)i) << 8) + (sl << 4));
            uint4 bv = *(const uint4*)(gBc + (((size_t)(uint32_t)j) << 8) + (sl << 4));
            __half2 r0 = __hmax2(__hadd2(*(__half2*)&av.x, *(__half2*)&bv.x), h2zero);
            __half2 r1 = __hmax2(__hadd2(*(__half2*)&av.y, *(__half2*)&bv.y), h2zero);
            __half2 r2 = __hmax2(__hadd2(*(__half2*)&av.z, *(__half2*)&bv.z), h2zero);
            __half2 r3 = __hmax2(__hadd2(*(__half2*)&av.w, *(__half2*)&bv.w), h2zero);
            uint32_t dst = KSrow + (uint32_t)(q2 << 8)
                         + (KC ^ (uint32_t)((q2 & 7) << 4));
            sts128(dst, *(uint32_t*)&r0, *(uint32_t*)&r1,
                        *(uint32_t*)&r2, *(uint32_t*)&r3);
        }
        __syncwarp();

        // ---- layer 2: 2 x (m16 x n64 x k128) fp16 MMA, fp32 accum ----
        float acc[2][8][4];
#pragma unroll
        for (int m = 0; m < 2; m++)
#pragma unroll
            for (int n = 0; n < 8; n++)
                acc[m][n][0] = acc[m][n][1] = acc[m][n][2] = acc[m][n][3] = 0.f;

#pragma unroll
        for (int s = 0; s < 8; s++) {           // k16 steps
            uint32_t A0[4], A1[4];
            ldsm_x4(A0[0], A0[1], A0[2], A0[3], KA0 ^ (uint32_t)(s << 5));
            ldsm_x4(A1[0], A1[1], A1[2], A1[3], (KA0 + 4096u) ^ (uint32_t)(s << 5));
#pragma unroll
            for (int nt = 0; nt < 8; nt++) {
                uint32_t b0, b1;
                ldsm_x2(b0, b1, (KB0 + (uint32_t)(nt << 11)) ^ (uint32_t)(s << 5));
                mma_fp16(acc[0][nt], A0[0], A0[1], A0[2], A0[3], b0, b1);
                mma_fp16(acc[1][nt], A1[0], A1[1], A1[2], A1[3], b0, b1);
            }
        }

        // ---- epilogue: relu(h2 + b2) . W3 + b3, reduced across the quad ----
#pragma unroll
        for (int m = 0; m < 2; m++) {
            float o0 = 0.f, o1 = 0.f;
#pragma unroll
            for (int n = 0; n < 8; n++) {
                int c0 = n * 8 + 2 * tg;
                float bb0 = b2s[c0], bb1 = b2s[c0 + 1];
                float w0 = w3s[c0],  w1 = w3s[c0 + 1];
                o0 += fmaxf(acc[m][n][0] + bb0, 0.f) * w0
                    + fmaxf(acc[m][n][1] + bb1, 0.f) * w1;
                o1 += fmaxf(acc[m][n][2] + bb0, 0.f) * w0
                    + fmaxf(acc[m][n][3] + bb1, 0.f) * w1;
            }
            o0 += __shfl_xor_sync(0xffffffffu, o0, 1);
            o0 += __shfl_xor_sync(0xffffffffu, o0, 2);
            o1 += __shfl_xor_sync(0xffffffffu, o1, 1);
            o1 += __shfl_xor_sync(0xffffffffu, o1, 2);
            if (tg == 0) {
                int e0 = ebase + m * 16 + g;
                int e1 = e0 + 8;
                if (e0 < E) out[e0] = o0 + b3v;
                if (e1 < E) out[e1] = o1 + b3v;
            }
        }
        __syncwarp();   // next tile's gather rewrites rows this warp just read
    }
}

// ---------------------------------------------------------------------------
// Launch
// ---------------------------------------------------------------------------
extern "C" void kernel_launch(void* const* d_in, const int* in_sizes, int n_in,
                              void* d_out, int out_size) {
    const float* drug = (const float*)d_in[0];
    const float* dis  = (const float*)d_in[1];
    const void*  eraw = d_in[2];
    const float* W1   = (const float*)d_in[3];
    const float* b1   = (const float*)d_in[4];
    const float* W2   = (const float*)d_in[5];
    const float* b2   = (const float*)d_in[6];
    const float* W3   = (const float*)d_in[7];
    const float* b3   = (const float*)d_in[8];
    float* out = (float*)d_out;

    int n_drug  = in_sizes[0] / IN_UNITS;
    int n_dis   = in_sizes[1] / IN_UNITS;
    int n_total = in_sizes[2];       // 2*E elements regardless of dtype
    int E       = n_total / 2;
    int ntiles  = (E + TILE_E - 1) / TILE_E;

    normalize_idx<<<(n_total + 255) / 256, 256>>>(eraw, n_total);
    precompute_A<<<(n_drug + RPB - 1) / RPB, IN_UNITS>>>(drug, W1, n_drug);
    precompute_B<<<(n_dis + RPB - 1) / RPB, IN_UNITS>>>(dis, W1, b1, n_dis);

    constexpr int smem_bytes =
        (TILE_E * H1_DIM + H2_DIM * H1_DIM) * 2 + 2 * H2_DIM * 4 + 256;
    cudaFuncSetAttribute(edge_mlp_kernel,
                         cudaFuncAttributeMaxDynamicSharedMemorySize,
                         smem_bytes);

    int grid = 296;  // persistent, 2 CTAs/SM
    if (grid > ntiles) grid = ntiles;
    edge_mlp_kernel<<<grid, NTHREADS, smem_bytes>>>(W2, b2, W3, b3, out, E, ntiles);
}

// round 10
// speedup vs baseline: 2.3052x; 1.1683x over previous
#include <cuda_runtime.h>
#include <cuda_fp16.h>
#include <cstdint>

// ---------------------------------------------------------------------------
// MLP over graph edges, factored:
//   h1 = relu(drug[i] @ W1a^T + dis[j] @ W1b^T + b1) = relu(A[i] + B[j])
//   h2 = relu(h1 @ W2^T + b2)       (FP16 tensor-core GEMM, fp32 accum)
//   out = h2 @ W3^T + b3            (register epilogue + quad shuffle reduce)
//
// R9: W2 fragments resident in registers (tile-invariant; 128 regs/thread),
// 4-warp CTAs @ 255-reg ceiling, 2 CTAs/SM. L1 bytes 1.5 -> 1.0 KB/edge.
// Precompute RPB 4 -> 16 (W1 re-read traffic /4).
// ---------------------------------------------------------------------------

#define IN_UNITS   128
#define H1_DIM     128
#define H2_DIM     64
#define N_DRUG_MAX 10000
#define N_DIS_MAX  5000
#define N_EDGE_MAX 2000000

#define WARP_E     32                 // edges per warp
#define NWARP      4
#define NTHREADS   (NWARP * 32)
#define TILE_E     (WARP_E * NWARP)   // 128 edges per CTA tile

__device__ __align__(16) __half g_Ah[N_DRUG_MAX * H1_DIM];
__device__ __align__(16) __half g_Bh[N_DIS_MAX * H1_DIM];
__device__ int g_ei[2 * N_EDGE_MAX];   // normalized int32 indices

__device__ __forceinline__ uint32_t smem_u32(const void* p) {
    return (uint32_t)__cvta_generic_to_shared(p);
}

__device__ __forceinline__ void ldsm_x4(uint32_t& r0, uint32_t& r1,
                                        uint32_t& r2, uint32_t& r3,
                                        uint32_t addr) {
    asm volatile("ldmatrix.sync.aligned.m8n8.x4.shared.b16 {%0,%1,%2,%3}, [%4];"
                 : "=r"(r0), "=r"(r1), "=r"(r2), "=r"(r3) : "r"(addr));
}
__device__ __forceinline__ void ldsm_x2(uint32_t& r0, uint32_t& r1,
                                        uint32_t addr) {
    asm volatile("ldmatrix.sync.aligned.m8n8.x2.shared.b16 {%0,%1}, [%2];"
                 : "=r"(r0), "=r"(r1) : "r"(addr));
}
__device__ __forceinline__ void sts128(uint32_t addr, uint32_t r0, uint32_t r1,
                                       uint32_t r2, uint32_t r3) {
    asm volatile("st.shared.v4.b32 [%0], {%1,%2,%3,%4};"
                 :: "r"(addr), "r"(r0), "r"(r1), "r"(r2), "r"(r3) : "memory");
}
__device__ __forceinline__ void mma_fp16(float acc[4],
        uint32_t a0, uint32_t a1, uint32_t a2, uint32_t a3,
        uint32_t b0, uint32_t b1) {
    asm volatile(
        "mma.sync.aligned.m16n8k16.row.col.f32.f16.f16.f32 "
        "{%0,%1,%2,%3}, {%4,%5,%6,%7}, {%8,%9}, {%0,%1,%2,%3};\n"
        : "+f"(acc[0]), "+f"(acc[1]), "+f"(acc[2]), "+f"(acc[3])
        : "r"(a0), "r"(a1), "r"(a2), "r"(a3), "r"(b0), "r"(b1));
}

// ---------------------------------------------------------------------------
// Index normalization (int64 vs int32 ambiguity in harness).
// ---------------------------------------------------------------------------
__global__ void normalize_idx(const void* __restrict__ raw, int n_total) {
    const unsigned long long* r64 = (const unsigned long long*)raw;
    const int* r32 = (const int*)raw;

    bool is64 = true;
    #pragma unroll
    for (int k = 0; k < 64; k++)
        if (r64[k] >> 32) { is64 = false; break; }

    int t = blockIdx.x * blockDim.x + threadIdx.x;
    if (t < n_total)
        g_ei[t] = is64 ? (int)((const long long*)raw)[t] : r32[t];
}

// ---------------------------------------------------------------------------
// Precompute (fp32 math, fp16 store), 16 rows/block to amortize W1 reads:
//   A[row] = drug_feat[row] @ W1[:, 0:128]^T
//   B[row] = dis_feat[row]  @ W1[:, 128:256]^T + b1
// ---------------------------------------------------------------------------
#define RPB 16

__global__ void precompute_A(const float* __restrict__ feat,
                             const float* __restrict__ W1, int nrows) {
    int row0 = blockIdx.x * RPB;
    int c = threadIdx.x;
    __shared__ float sf[RPB][IN_UNITS];
    for (int r = 0; r < RPB; r++) {
        int row = row0 + r;
        sf[r][c] = (row < nrows) ? feat[row * IN_UNITS + c] : 0.f;
    }
    __syncthreads();
    float acc[RPB];
#pragma unroll
    for (int r = 0; r < RPB; r++) acc[r] = 0.f;
    const float4* w = (const float4*)(W1 + c * (2 * IN_UNITS));
#pragma unroll 8
    for (int k = 0; k < IN_UNITS / 4; k++) {
        float4 ww = w[k];
#pragma unroll
        for (int r = 0; r < RPB; r++) {
            float4 f = *(const float4*)&sf[r][k * 4];
            acc[r] += f.x * ww.x + f.y * ww.y + f.z * ww.z + f.w * ww.w;
        }
    }
    for (int r = 0; r < RPB; r++) {
        int row = row0 + r;
        if (row < nrows) g_Ah[row * H1_DIM + c] = __float2half_rn(acc[r]);
    }
}

__global__ void precompute_B(const float* __restrict__ feat,
                             const float* __restrict__ W1,
                             const float* __restrict__ b1, int nrows) {
    int row0 = blockIdx.x * RPB;
    int c = threadIdx.x;
    __shared__ float sf[RPB][IN_UNITS];
    for (int r = 0; r < RPB; r++) {
        int row = row0 + r;
        sf[r][c] = (row < nrows) ? feat[row * IN_UNITS + c] : 0.f;
    }
    __syncthreads();
    float b1c = b1[c];
    float acc[RPB];
#pragma unroll
    for (int r = 0; r < RPB; r++) acc[r] = b1c;
    const float4* w = (const float4*)(W1 + c * (2 * IN_UNITS) + IN_UNITS);
#pragma unroll 8
    for (int k = 0; k < IN_UNITS / 4; k++) {
        float4 ww = w[k];
#pragma unroll
        for (int r = 0; r < RPB; r++) {
            float4 f = *(const float4*)&sf[r][k * 4];
            acc[r] += f.x * ww.x + f.y * ww.y + f.z * ww.z + f.w * ww.w;
        }
    }
    for (int r = 0; r < RPB; r++) {
        int row = row0 + r;
        if (row < nrows) g_Bh[row * H1_DIM + c] = __float2half_rn(acc[r]);
    }
}

// ---------------------------------------------------------------------------
// Main fused kernel. SMEM (fp16, XOR-swizzled, 16B chunk granularity):
//   H1h:  TILE_E rows x 256B (16 chunks/row; phys chunk = c ^ (row&7))
//   W2h:  64 rows x 256B, same swizzle (read ONCE into regs, then unused)
// W2 B-fragments are register-resident across the whole tile loop.
// ---------------------------------------------------------------------------
__global__ __launch_bounds__(NTHREADS, 1)
void edge_mlp_kernel(const float* __restrict__ W2,
                     const float* __restrict__ b2,
                     const float* __restrict__ W3,
                     const float* __restrict__ b3,
                     float* __restrict__ out,
                     int E, int ntiles) {
    extern __shared__ char smraw[];
    // 256B-align the working base so the chunk field (bits 4..7) is pure.
    uint32_t s0 = smem_u32(smraw);
    uint32_t padb = ((s0 + 255u) & ~255u) - s0;
    char* smbase = smraw + padb;
    __half* H1h = (__half*)smbase;                 // TILE_E * 128 halves
    __half* W2h = H1h + TILE_E * H1_DIM;           // 64 * 128 halves
    float*  b2s = (float*)(W2h + H2_DIM * H1_DIM); // 64
    float*  w3s = b2s + H2_DIM;                    // 64

    int tid = threadIdx.x;

    // Stage W2 (fp16, swizzled), b2, W3 once per CTA.
    for (int t = tid; t < H2_DIM * H1_DIM; t += NTHREADS) {
        int n = t >> 7, k = t & 127;
        int phys = n * H1_DIM + (((k >> 3) ^ (n & 7)) << 3) + (k & 7);
        W2h[phys] = __float2half_rn(W2[t]);
    }
    if (tid < H2_DIM) { b2s[tid] = b2[tid]; w3s[tid] = W3[tid]; }
    __syncthreads();
    float b3v = __ldg(b3);

    int warp = tid >> 5;
    int lane = tid & 31;
    int g  = lane >> 2;   // mma groupID
    int tg = lane & 3;    // mma thread-in-group
    uint32_t hw_u32 = smem_u32(H1h) + warp * (WARP_E * 256);  // 8KB/warp
    uint32_t w2_u32 = smem_u32(W2h);

    // ---- address constants ----
    int sl = lane & 15;
    int hh = lane >> 4;
    uint32_t KSrow = hw_u32 + ((uint32_t)hh << 8);
    uint32_t KC    = (uint32_t)((sl ^ hh) << 4);
    int ar = lane & 15;
    int ac_hi = lane >> 4;
    uint32_t KA0 = hw_u32 + (ar << 8) + ((((ar & 7) ^ ac_hi)) << 4);
    int bn = lane & 7;
    int bc_hi = (lane >> 3) & 1;
    uint32_t KB0 = w2_u32 + (bn << 8) + (((bn ^ bc_hi)) << 4);

    // ---- preload ALL W2 B-fragments into registers (tile-invariant) ----
    uint32_t Bf[8][8][2];
#pragma unroll
    for (int s = 0; s < 8; s++)
#pragma unroll
        for (int nt = 0; nt < 8; nt++)
            ldsm_x2(Bf[s][nt][0], Bf[s][nt][1],
                    (KB0 + (uint32_t)(nt << 11)) ^ (uint32_t)(s << 5));

    const __half2 h2zero = __floats2half2_rn(0.f, 0.f);
    const char* gAc = (const char*)g_Ah;
    const char* gBc = (const char*)g_Bh;

    for (int tile = blockIdx.x; tile < ntiles; tile += gridDim.x) {
        int ebase = tile * TILE_E + warp * WARP_E;

        // Per-lane indices for 32 edges (drug + dis), coalesced.
        int e = ebase + lane;
        int idx_d = 0, idx_s = 0;
        if (e < E) {
            idx_d = g_ei[e];
            idx_s = g_ei[E + e];
        }

        // ---- gather: 2 edges/iteration, 16B per lane ----
#pragma unroll
        for (int q2 = 0; q2 < WARP_E; q2 += 2) {
            int qq = q2 + hh;
            int i = __shfl_sync(0xffffffffu, idx_d, qq);
            int j = __shfl_sync(0xffffffffu, idx_s, qq);
            uint4 av = *(const uint4*)(gAc + (((size_t)(uint32_t)i) << 8) + (sl << 4));
            uint4 bv = *(const uint4*)(gBc + (((size_t)(uint32_t)j) << 8) + (sl << 4));
            __half2 r0 = __hmax2(__hadd2(*(__half2*)&av.x, *(__half2*)&bv.x), h2zero);
            __half2 r1 = __hmax2(__hadd2(*(__half2*)&av.y, *(__half2*)&bv.y), h2zero);
            __half2 r2 = __hmax2(__hadd2(*(__half2*)&av.z, *(__half2*)&bv.z), h2zero);
            __half2 r3 = __hmax2(__hadd2(*(__half2*)&av.w, *(__half2*)&bv.w), h2zero);
            uint32_t dst = KSrow + (uint32_t)(q2 << 8)
                         + (KC ^ (uint32_t)((q2 & 7) << 4));
            sts128(dst, *(uint32_t*)&r0, *(uint32_t*)&r1,
                        *(uint32_t*)&r2, *(uint32_t*)&r3);
        }
        __syncwarp();

        // ---- layer 2: 2 x (m16 x n64 x k128) fp16 MMA, fp32 accum ----
        float acc[2][8][4];
#pragma unroll
        for (int m = 0; m < 2; m++)
#pragma unroll
            for (int n = 0; n < 8; n++)
                acc[m][n][0] = acc[m][n][1] = acc[m][n][2] = acc[m][n][3] = 0.f;

#pragma unroll
        for (int s = 0; s < 8; s++) {           // k16 steps
            uint32_t A0[4], A1[4];
            ldsm_x4(A0[0], A0[1], A0[2], A0[3], KA0 ^ (uint32_t)(s << 5));
            ldsm_x4(A1[0], A1[1], A1[2], A1[3], (KA0 + 4096u) ^ (uint32_t)(s << 5));
#pragma unroll
            for (int nt = 0; nt < 8; nt++) {
                mma_fp16(acc[0][nt], A0[0], A0[1], A0[2], A0[3],
                         Bf[s][nt][0], Bf[s][nt][1]);
                mma_fp16(acc[1][nt], A1[0], A1[1], A1[2], A1[3],
                         Bf[s][nt][0], Bf[s][nt][1]);
            }
        }

        // ---- epilogue: relu(h2 + b2) . W3 + b3, reduced across the quad ----
#pragma unroll
        for (int m = 0; m < 2; m++) {
            float o0 = 0.f, o1 = 0.f;
#pragma unroll
            for (int n = 0; n < 8; n++) {
                int c0 = n * 8 + 2 * tg;
                float bb0 = b2s[c0], bb1 = b2s[c0 + 1];
                float w0 = w3s[c0],  w1 = w3s[c0 + 1];
                o0 += fmaxf(acc[m][n][0] + bb0, 0.f) * w0
                    + fmaxf(acc[m][n][1] + bb1, 0.f) * w1;
                o1 += fmaxf(acc[m][n][2] + bb0, 0.f) * w0
                    + fmaxf(acc[m][n][3] + bb1, 0.f) * w1;
            }
            o0 += __shfl_xor_sync(0xffffffffu, o0, 1);
            o0 += __shfl_xor_sync(0xffffffffu, o0, 2);
            o1 += __shfl_xor_sync(0xffffffffu, o1, 1);
            o1 += __shfl_xor_sync(0xffffffffu, o1, 2);
            if (tg == 0) {
                int e0 = ebase + m * 16 + g;
                int e1 = e0 + 8;
                if (e0 < E) out[e0] = o0 + b3v;
                if (e1 < E) out[e1] = o1 + b3v;
            }
        }
        __syncwarp();   // next tile's gather rewrites rows this warp just read
    }
}

// ---------------------------------------------------------------------------
// Launch
// ---------------------------------------------------------------------------
extern "C" void kernel_launch(void* const* d_in, const int* in_sizes, int n_in,
                              void* d_out, int out_size) {
    const float* drug = (const float*)d_in[0];
    const float* dis  = (const float*)d_in[1];
    const void*  eraw = d_in[2];
    const float* W1   = (const float*)d_in[3];
    const float* b1   = (const float*)d_in[4];
    const float* W2   = (const float*)d_in[5];
    const float* b2   = (const float*)d_in[6];
    const float* W3   = (const float*)d_in[7];
    const float* b3   = (const float*)d_in[8];
    float* out = (float*)d_out;

    int n_drug  = in_sizes[0] / IN_UNITS;
    int n_dis   = in_sizes[1] / IN_UNITS;
    int n_total = in_sizes[2];       // 2*E elements regardless of dtype
    int E       = n_total / 2;
    int ntiles  = (E + TILE_E - 1) / TILE_E;

    normalize_idx<<<(n_total + 255) / 256, 256>>>(eraw, n_total);
    precompute_A<<<(n_drug + RPB - 1) / RPB, IN_UNITS>>>(drug, W1, n_drug);
    precompute_B<<<(n_dis + RPB - 1) / RPB, IN_UNITS>>>(dis, W1, b1, n_dis);

    constexpr int smem_bytes =
        (TILE_E * H1_DIM + H2_DIM * H1_DIM) * 2 + 2 * H2_DIM * 4 + 256;  // ~49 KB
    cudaFuncSetAttribute(edge_mlp_kernel,
                         cudaFuncAttributeMaxDynamicSharedMemorySize,
                         smem_bytes);

    int grid = 296;  // persistent, 2 CTAs/SM (reg-limited: 128 thr x ~230 regs)
    if (grid > ntiles) grid = ntiles;
    edge_mlp_kernel<<<grid, NTHREADS, smem_bytes>>>(W2, b2, W3, b3, out, E, ntiles);
}

// round 11
// speedup vs baseline: 2.5133x; 1.0903x over previous
#include <cuda_runtime.h>
#include <cuda_fp16.h>
#include <cstdint>

// ---------------------------------------------------------------------------
// MLP over graph edges, factored:
//   h1 = relu(drug[i] @ W1a^T + dis[j] @ W1b^T + b1) = relu(A[i] + B[j])
//   h2 = relu(h1 @ W2^T + b2)       (FP16 tensor-core GEMM, fp32 accum)
//   out = h2 @ W3^T + b3            (register epilogue + quad shuffle reduce)
//
// R10: hybrid W2 residency — k-steps 0..3 in registers (64 regs), 4..7 via
// ldsm per tile. 1.25 KB L1/edge at 12 warps/SM (3 CTAs x 4 warps, <=168
// regs). Precompute RPB=32, A/B merged into one launch.
// ---------------------------------------------------------------------------

#define IN_UNITS   128
#define H1_DIM     128
#define H2_DIM     64
#define N_DRUG_MAX 10000
#define N_DIS_MAX  5000
#define N_EDGE_MAX 2000000

#define WARP_E     32                 // edges per warp
#define NWARP      4
#define NTHREADS   (NWARP * 32)
#define TILE_E     (WARP_E * NWARP)   // 128 edges per CTA tile
#define S_REG      4                  // k16 steps whose B-fragments live in regs

__device__ __align__(16) __half g_Ah[N_DRUG_MAX * H1_DIM];
__device__ __align__(16) __half g_Bh[N_DIS_MAX * H1_DIM];
__device__ int g_ei[2 * N_EDGE_MAX];   // normalized int32 indices

__device__ __forceinline__ uint32_t smem_u32(const void* p) {
    return (uint32_t)__cvta_generic_to_shared(p);
}

__device__ __forceinline__ void ldsm_x4(uint32_t& r0, uint32_t& r1,
                                        uint32_t& r2, uint32_t& r3,
                                        uint32_t addr) {
    asm volatile("ldmatrix.sync.aligned.m8n8.x4.shared.b16 {%0,%1,%2,%3}, [%4];"
                 : "=r"(r0), "=r"(r1), "=r"(r2), "=r"(r3) : "r"(addr));
}
__device__ __forceinline__ void ldsm_x2(uint32_t& r0, uint32_t& r1,
                                        uint32_t addr) {
    asm volatile("ldmatrix.sync.aligned.m8n8.x2.shared.b16 {%0,%1}, [%2];"
                 : "=r"(r0), "=r"(r1) : "r"(addr));
}
__device__ __forceinline__ void sts128(uint32_t addr, uint32_t r0, uint32_t r1,
                                       uint32_t r2, uint32_t r3) {
    asm volatile("st.shared.v4.b32 [%0], {%1,%2,%3,%4};"
                 :: "r"(addr), "r"(r0), "r"(r1), "r"(r2), "r"(r3) : "memory");
}
__device__ __forceinline__ void mma_fp16(float acc[4],
        uint32_t a0, uint32_t a1, uint32_t a2, uint32_t a3,
        uint32_t b0, uint32_t b1) {
    asm volatile(
        "mma.sync.aligned.m16n8k16.row.col.f32.f16.f16.f32 "
        "{%0,%1,%2,%3}, {%4,%5,%6,%7}, {%8,%9}, {%0,%1,%2,%3};\n"
        : "+f"(acc[0]), "+f"(acc[1]), "+f"(acc[2]), "+f"(acc[3])
        : "r"(a0), "r"(a1), "r"(a2), "r"(a3), "r"(b0), "r"(b1));
}

// ---------------------------------------------------------------------------
// Index normalization (int64 vs int32 ambiguity in harness).
// ---------------------------------------------------------------------------
__global__ void normalize_idx(const void* __restrict__ raw, int n_total) {
    const unsigned long long* r64 = (const unsigned long long*)raw;
    const int* r32 = (const int*)raw;

    bool is64 = true;
    #pragma unroll
    for (int k = 0; k < 64; k++)
        if (r64[k] >> 32) { is64 = false; break; }

    int t = blockIdx.x * blockDim.x + threadIdx.x;
    if (t < n_total)
        g_ei[t] = is64 ? (int)((const long long*)raw)[t] : r32[t];
}

// ---------------------------------------------------------------------------
// Precompute (fp32 math, fp16 store), 32 rows/block, A and B in ONE launch:
//   blocks [0, nblkA)      : A[row] = drug_feat[row] @ W1[:, 0:128]^T
//   blocks [nblkA, total)  : B[row] = dis_feat[row]  @ W1[:, 128:256]^T + b1
// ---------------------------------------------------------------------------
#define RPB 32

__global__ void precompute_AB(const float* __restrict__ drug,
                              const float* __restrict__ dis,
                              const float* __restrict__ W1,
                              const float* __restrict__ b1,
                              int n_drug, int n_dis, int nblkA) {
    bool isA = (int)blockIdx.x < nblkA;
    const float* feat = isA ? drug : dis;
    int nrows  = isA ? n_drug : n_dis;
    int row0   = (isA ? blockIdx.x : blockIdx.x - nblkA) * RPB;
    int c = threadIdx.x;

    __shared__ float sf[RPB][IN_UNITS];
    for (int r = 0; r < RPB; r++) {
        int row = row0 + r;
        sf[r][c] = (row < nrows) ? feat[row * IN_UNITS + c] : 0.f;
    }
    __syncthreads();

    float init = isA ? 0.f : b1[c];
    float acc[RPB];
#pragma unroll
    for (int r = 0; r < RPB; r++) acc[r] = init;

    const float4* w = (const float4*)(W1 + c * (2 * IN_UNITS) + (isA ? 0 : IN_UNITS));
#pragma unroll 4
    for (int k = 0; k < IN_UNITS / 4; k++) {
        float4 ww = w[k];
#pragma unroll
        for (int r = 0; r < RPB; r++) {
            float4 f = *(const float4*)&sf[r][k * 4];
            acc[r] += f.x * ww.x + f.y * ww.y + f.z * ww.z + f.w * ww.w;
        }
    }
    __half* dst = isA ? g_Ah : g_Bh;
    for (int r = 0; r < RPB; r++) {
        int row = row0 + r;
        if (row < nrows) dst[row * H1_DIM + c] = __float2half_rn(acc[r]);
    }
}

// ---------------------------------------------------------------------------
// Main fused kernel. SMEM (fp16, XOR-swizzled, 16B chunk granularity):
//   H1h:  TILE_E rows x 256B (16 chunks/row; phys chunk = c ^ (row&7))
//   W2h:  64 rows x 256B, same swizzle
// B-fragments: s<S_REG register-resident, rest ldsm'd per tile.
// ---------------------------------------------------------------------------
__global__ __launch_bounds__(NTHREADS, 3)
void edge_mlp_kernel(const float* __restrict__ W2,
                     const float* __restrict__ b2,
                     const float* __restrict__ W3,
                     const float* __restrict__ b3,
                     float* __restrict__ out,
                     int E, int ntiles) {
    extern __shared__ char smraw[];
    // 256B-align the working base so the chunk field (bits 4..7) is pure.
    uint32_t s0 = smem_u32(smraw);
    uint32_t padb = ((s0 + 255u) & ~255u) - s0;
    char* smbase = smraw + padb;
    __half* H1h = (__half*)smbase;                 // TILE_E * 128 halves
    __half* W2h = H1h + TILE_E * H1_DIM;           // 64 * 128 halves
    float*  b2s = (float*)(W2h + H2_DIM * H1_DIM); // 64
    float*  w3s = b2s + H2_DIM;                    // 64

    int tid = threadIdx.x;

    // Stage W2 (fp16, swizzled), b2, W3 once per CTA.
    for (int t = tid; t < H2_DIM * H1_DIM; t += NTHREADS) {
        int n = t >> 7, k = t & 127;
        int phys = n * H1_DIM + (((k >> 3) ^ (n & 7)) << 3) + (k & 7);
        W2h[phys] = __float2half_rn(W2[t]);
    }
    if (tid < H2_DIM) { b2s[tid] = b2[tid]; w3s[tid] = W3[tid]; }
    __syncthreads();
    float b3v = __ldg(b3);

    int warp = tid >> 5;
    int lane = tid & 31;
    int g  = lane >> 2;   // mma groupID
    int tg = lane & 3;    // mma thread-in-group
    uint32_t hw_u32 = smem_u32(H1h) + warp * (WARP_E * 256);  // 8KB/warp
    uint32_t w2_u32 = smem_u32(W2h);

    // ---- address constants ----
    int sl = lane & 15;
    int hh = lane >> 4;
    uint32_t KSrow = hw_u32 + ((uint32_t)hh << 8);
    uint32_t KC    = (uint32_t)((sl ^ hh) << 4);
    int ar = lane & 15;
    int ac_hi = lane >> 4;
    uint32_t KA0 = hw_u32 + (ar << 8) + ((((ar & 7) ^ ac_hi)) << 4);
    int bn = lane & 7;
    int bc_hi = (lane >> 3) & 1;
    uint32_t KB0 = w2_u32 + (bn << 8) + (((bn ^ bc_hi)) << 4);

    // ---- preload B-fragments for k-steps 0..S_REG-1 (tile-invariant) ----
    uint32_t Bf[S_REG][8][2];
#pragma unroll
    for (int s = 0; s < S_REG; s++)
#pragma unroll
        for (int nt = 0; nt < 8; nt++)
            ldsm_x2(Bf[s][nt][0], Bf[s][nt][1],
                    (KB0 + (uint32_t)(nt << 11)) ^ (uint32_t)(s << 5));

    const __half2 h2zero = __floats2half2_rn(0.f, 0.f);
    const char* gAc = (const char*)g_Ah;
    const char* gBc = (const char*)g_Bh;

    for (int tile = blockIdx.x; tile < ntiles; tile += gridDim.x) {
        int ebase = tile * TILE_E + warp * WARP_E;

        // Per-lane indices for 32 edges (drug + dis), coalesced.
        int e = ebase + lane;
        int idx_d = 0, idx_s = 0;
        if (e < E) {
            idx_d = g_ei[e];
            idx_s = g_ei[E + e];
        }

        // ---- gather: 2 edges/iteration, 16B per lane ----
#pragma unroll
        for (int q2 = 0; q2 < WARP_E; q2 += 2) {
            int qq = q2 + hh;
            int i = __shfl_sync(0xffffffffu, idx_d, qq);
            int j = __shfl_sync(0xffffffffu, idx_s, qq);
            uint4 av = *(const uint4*)(gAc + (((size_t)(uint32_t)i) << 8) + (sl << 4));
            uint4 bv = *(const uint4*)(gBc + (((size_t)(uint32_t)j) << 8) + (sl << 4));
            __half2 r0 = __hmax2(__hadd2(*(__half2*)&av.x, *(__half2*)&bv.x), h2zero);
            __half2 r1 = __hmax2(__hadd2(*(__half2*)&av.y, *(__half2*)&bv.y), h2zero);
            __half2 r2 = __hmax2(__hadd2(*(__half2*)&av.z, *(__half2*)&bv.z), h2zero);
            __half2 r3 = __hmax2(__hadd2(*(__half2*)&av.w, *(__half2*)&bv.w), h2zero);
            uint32_t dst = KSrow + (uint32_t)(q2 << 8)
                         + (KC ^ (uint32_t)((q2 & 7) << 4));
            sts128(dst, *(uint32_t*)&r0, *(uint32_t*)&r1,
                        *(uint32_t*)&r2, *(uint32_t*)&r3);
        }
        __syncwarp();

        // ---- layer 2: 2 x (m16 x n64 x k128) fp16 MMA, fp32 accum ----
        float acc[2][8][4];
#pragma unroll
        for (int m = 0; m < 2; m++)
#pragma unroll
            for (int n = 0; n < 8; n++)
                acc[m][n][0] = acc[m][n][1] = acc[m][n][2] = acc[m][n][3] = 0.f;

#pragma unroll
        for (int s = 0; s < 8; s++) {           // k16 steps
            uint32_t A0[4], A1[4];
            ldsm_x4(A0[0], A0[1], A0[2], A0[3], KA0 ^ (uint32_t)(s << 5));
            ldsm_x4(A1[0], A1[1], A1[2], A1[3], (KA0 + 4096u) ^ (uint32_t)(s << 5));
#pragma unroll
            for (int nt = 0; nt < 8; nt++) {
                uint32_t b0, b1;
                if (s < S_REG) {
                    b0 = Bf[s][nt][0];
                    b1 = Bf[s][nt][1];
                } else {
                    ldsm_x2(b0, b1,
                            (KB0 + (uint32_t)(nt << 11)) ^ (uint32_t)(s << 5));
                }
                mma_fp16(acc[0][nt], A0[0], A0[1], A0[2], A0[3], b0, b1);
                mma_fp16(acc[1][nt], A1[0], A1[1], A1[2], A1[3], b0, b1);
            }
        }

        // ---- epilogue: relu(h2 + b2) . W3 + b3, reduced across the quad ----
#pragma unroll
        for (int m = 0; m < 2; m++) {
            float o0 = 0.f, o1 = 0.f;
#pragma unroll
            for (int n = 0; n < 8; n++) {
                int c0 = n * 8 + 2 * tg;
                float bb0 = b2s[c0], bb1 = b2s[c0 + 1];
                float w0 = w3s[c0],  w1 = w3s[c0 + 1];
                o0 += fmaxf(acc[m][n][0] + bb0, 0.f) * w0
                    + fmaxf(acc[m][n][1] + bb1, 0.f) * w1;
                o1 += fmaxf(acc[m][n][2] + bb0, 0.f) * w0
                    + fmaxf(acc[m][n][3] + bb1, 0.f) * w1;
            }
            o0 += __shfl_xor_sync(0xffffffffu, o0, 1);
            o0 += __shfl_xor_sync(0xffffffffu, o0, 2);
            o1 += __shfl_xor_sync(0xffffffffu, o1, 1);
            o1 += __shfl_xor_sync(0xffffffffu, o1, 2);
            if (tg == 0) {
                int e0 = ebase + m * 16 + g;
                int e1 = e0 + 8;
                if (e0 < E) out[e0] = o0 + b3v;
                if (e1 < E) out[e1] = o1 + b3v;
            }
        }
        __syncwarp();   // next tile's gather rewrites rows this warp just read
    }
}

// ---------------------------------------------------------------------------
// Launch
// ---------------------------------------------------------------------------
extern "C" void kernel_launch(void* const* d_in, const int* in_sizes, int n_in,
                              void* d_out, int out_size) {
    const float* drug = (const float*)d_in[0];
    const float* dis  = (const float*)d_in[1];
    const void*  eraw = d_in[2];
    const float* W1   = (const float*)d_in[3];
    const float* b1   = (const float*)d_in[4];
    const float* W2   = (const float*)d_in[5];
    const float* b2   = (const float*)d_in[6];
    const float* W3   = (const float*)d_in[7];
    const float* b3   = (const float*)d_in[8];
    float* out = (float*)d_out;

    int n_drug  = in_sizes[0] / IN_UNITS;
    int n_dis   = in_sizes[1] / IN_UNITS;
    int n_total = in_sizes[2];       // 2*E elements regardless of dtype
    int E       = n_total / 2;
    int ntiles  = (E + TILE_E - 1) / TILE_E;

    normalize_idx<<<(n_total + 255) / 256, 256>>>(eraw, n_total);

    int nblkA = (n_drug + RPB - 1) / RPB;
    int nblkB = (n_dis + RPB - 1) / RPB;
    precompute_AB<<<nblkA + nblkB, IN_UNITS>>>(drug, dis, W1, b1,
                                               n_drug, n_dis, nblkA);

    constexpr int smem_bytes =
        (TILE_E * H1_DIM + H2_DIM * H1_DIM) * 2 + 2 * H2_DIM * 4 + 256;  // ~49 KB
    cudaFuncSetAttribute(edge_mlp_kernel,
                         cudaFuncAttributeMaxDynamicSharedMemorySize,
                         smem_bytes);

    int grid = 444;  // persistent, 3 CTAs/SM (12 warps/SM)
    if (grid > ntiles) grid = ntiles;
    edge_mlp_kernel<<<grid, NTHREADS, smem_bytes>>>(W2, b2, W3, b3, out, E, ntiles);
}

// round 13
// speedup vs baseline: 2.6515x; 1.0550x over previous
#include <cuda_runtime.h>
#include <cuda_fp16.h>
#include <cstdint>

// ---------------------------------------------------------------------------
// MLP over graph edges, factored:
//   h1 = relu(drug[i] @ W1a^T + dis[j] @ W1b^T + b1) = relu(A[i] + B[j])
//   h2 = relu(h1 @ W2^T + b2)       (FP16 tensor-core GEMM, fp32 accum)
//   out = h2 @ W3^T + b3            (register epilogue + quad shuffle reduce)
//
// R11/R12: normalize_idx kernel removed — int64/int32 edge-index detection
// is done once per CTA in-kernel; indices read directly from the input
// buffer. Main loop unchanged from R10 (hybrid W2 residency, 12 warps/SM).
// ---------------------------------------------------------------------------

#define IN_UNITS   128
#define H1_DIM     128
#define H2_DIM     64

#define WARP_E     32                 // edges per warp
#define NWARP      4
#define NTHREADS   (NWARP * 32)
#define TILE_E     (WARP_E * NWARP)   // 128 edges per CTA tile
#define S_REG      4                  // k16 steps whose B-fragments live in regs

#define N_DRUG_MAX 10000
#define N_DIS_MAX  5000

__device__ __align__(16) __half g_Ah[N_DRUG_MAX * H1_DIM];
__device__ __align__(16) __half g_Bh[N_DIS_MAX * H1_DIM];

__device__ __forceinline__ uint32_t smem_u32(const void* p) {
    return (uint32_t)__cvta_generic_to_shared(p);
}

__device__ __forceinline__ void ldsm_x4(uint32_t& r0, uint32_t& r1,
                                        uint32_t& r2, uint32_t& r3,
                                        uint32_t addr) {
    asm volatile("ldmatrix.sync.aligned.m8n8.x4.shared.b16 {%0,%1,%2,%3}, [%4];"
                 : "=r"(r0), "=r"(r1), "=r"(r2), "=r"(r3) : "r"(addr));
}
__device__ __forceinline__ void ldsm_x2(uint32_t& r0, uint32_t& r1,
                                        uint32_t addr) {
    asm volatile("ldmatrix.sync.aligned.m8n8.x2.shared.b16 {%0,%1}, [%2];"
                 : "=r"(r0), "=r"(r1) : "r"(addr));
}
__device__ __forceinline__ void sts128(uint32_t addr, uint32_t r0, uint32_t r1,
                                       uint32_t r2, uint32_t r3) {
    asm volatile("st.shared.v4.b32 [%0], {%1,%2,%3,%4};"
                 :: "r"(addr), "r"(r0), "r"(r1), "r"(r2), "r"(r3) : "memory");
}
__device__ __forceinline__ void mma_fp16(float acc[4],
        uint32_t a0, uint32_t a1, uint32_t a2, uint32_t a3,
        uint32_t b0, uint32_t b1) {
    asm volatile(
        "mma.sync.aligned.m16n8k16.row.col.f32.f16.f16.f32 "
        "{%0,%1,%2,%3}, {%4,%5,%6,%7}, {%8,%9}, {%0,%1,%2,%3};\n"
        : "+f"(acc[0]), "+f"(acc[1]), "+f"(acc[2]), "+f"(acc[3])
        : "r"(a0), "r"(a1), "r"(a2), "r"(a3), "r"(b0), "r"(b1));
}

// ---------------------------------------------------------------------------
// Precompute (fp32 math, fp16 store), 32 rows/block, A and B in ONE launch:
//   blocks [0, nblkA)      : A[row] = drug_feat[row] @ W1[:, 0:128]^T
//   blocks [nblkA, total)  : B[row] = dis_feat[row]  @ W1[:, 128:256]^T + b1
// ---------------------------------------------------------------------------
#define RPB 32

__global__ void precompute_AB(const float* __restrict__ drug,
                              const float* __restrict__ dis,
                              const float* __restrict__ W1,
                              const float* __restrict__ b1,
                              int n_drug, int n_dis, int nblkA) {
    bool isA = (int)blockIdx.x < nblkA;
    const float* feat = isA ? drug : dis;
    int nrows  = isA ? n_drug : n_dis;
    int row0   = (isA ? blockIdx.x : blockIdx.x - nblkA) * RPB;
    int c = threadIdx.x;

    __shared__ float sf[RPB][IN_UNITS];
    for (int r = 0; r < RPB; r++) {
        int row = row0 + r;
        sf[r][c] = (row < nrows) ? feat[row * IN_UNITS + c] : 0.f;
    }
    __syncthreads();

    float init = isA ? 0.f : b1[c];
    float acc[RPB];
#pragma unroll
    for (int r = 0; r < RPB; r++) acc[r] = init;

    const float4* w = (const float4*)(W1 + c * (2 * IN_UNITS) + (isA ? 0 : IN_UNITS));
#pragma unroll 4
    for (int k = 0; k < IN_UNITS / 4; k++) {
        float4 ww = w[k];
#pragma unroll
        for (int r = 0; r < RPB; r++) {
            float4 f = *(const float4*)&sf[r][k * 4];
            acc[r] += f.x * ww.x + f.y * ww.y + f.z * ww.z + f.w * ww.w;
        }
    }
    __half* dst = isA ? g_Ah : g_Bh;
    for (int r = 0; r < RPB; r++) {
        int row = row0 + r;
        if (row < nrows) dst[row * H1_DIM + c] = __float2half_rn(acc[r]);
    }
}

// ---------------------------------------------------------------------------
// Main fused kernel. SMEM (fp16, XOR-swizzled, 16B chunk granularity):
//   H1h:  TILE_E rows x 256B (16 chunks/row; phys chunk = c ^ (row&7))
//   W2h:  64 rows x 256B, same swizzle
// B-fragments: s<S_REG register-resident, rest ldsm'd per tile.
// Edge-index dtype (int64 vs int32) detected once per CTA: with int64 data
// every value < 5000 so the hi word of each of the first 64 u64 words is 0;
// with int32 data a hi word is the next index (nonzero w.p. 4999/5000).
// ---------------------------------------------------------------------------
__global__ __launch_bounds__(NTHREADS, 3)
void edge_mlp_kernel(const void* __restrict__ eraw,
                     const float* __restrict__ W2,
                     const float* __restrict__ b2,
                     const float* __restrict__ W3,
                     const float* __restrict__ b3,
                     float* __restrict__ out,
                     int E, int ntiles) {
    extern __shared__ char smraw[];
    // 256B-align the working base so the chunk field (bits 4..7) is pure.
    uint32_t s0 = smem_u32(smraw);
    uint32_t padb = ((s0 + 255u) & ~255u) - s0;
    char* smbase = smraw + padb;
    __half* H1h = (__half*)smbase;                 // TILE_E * 128 halves
    __half* W2h = H1h + TILE_E * H1_DIM;           // 64 * 128 halves
    float*  b2s = (float*)(W2h + H2_DIM * H1_DIM); // 64
    float*  w3s = b2s + H2_DIM;                    // 64
    __shared__ int s_is64;

    int tid = threadIdx.x;

    // Detect index dtype once per CTA.
    if (tid == 0) {
        const unsigned long long* r64 = (const unsigned long long*)eraw;
        int is64 = 1;
        #pragma unroll 8
        for (int k = 0; k < 64; k++)
            if (r64[k] >> 32) { is64 = 0; break; }
        s_is64 = is64;
    }

    // Stage W2 (fp16, swizzled), b2, W3 once per CTA.
    for (int t = tid; t < H2_DIM * H1_DIM; t += NTHREADS) {
        int n = t >> 7, k = t & 127;
        int phys = n * H1_DIM + (((k >> 3) ^ (n & 7)) << 3) + (k & 7);
        W2h[phys] = __float2half_rn(W2[t]);
    }
    if (tid < H2_DIM) { b2s[tid] = b2[tid]; w3s[tid] = W3[tid]; }
    __syncthreads();
    float b3v = __ldg(b3);
    bool is64 = (s_is64 != 0);
    const long long* e64 = (const long long*)eraw;
    const int*       e32 = (const int*)eraw;

    int warp = tid >> 5;
    int lane = tid & 31;
    int g  = lane >> 2;   // mma groupID
    int tg = lane & 3;    // mma thread-in-group
    uint32_t hw_u32 = smem_u32(H1h) + warp * (WARP_E * 256);  // 8KB/warp
    uint32_t w2_u32 = smem_u32(W2h);

    // ---- address constants ----
    int sl = lane & 15;
    int hh = lane >> 4;
    uint32_t KSrow = hw_u32 + ((uint32_t)hh << 8);
    uint32_t KC    = (uint32_t)((sl ^ hh) << 4);
    int ar = lane & 15;
    int ac_hi = lane >> 4;
    uint32_t KA0 = hw_u32 + (ar << 8) + ((((ar & 7) ^ ac_hi)) << 4);
    int bn = lane & 7;
    int bc_hi = (lane >> 3) & 1;
    uint32_t KB0 = w2_u32 + (bn << 8) + (((bn ^ bc_hi)) << 4);

    // ---- preload B-fragments for k-steps 0..S_REG-1 (tile-invariant) ----
    uint32_t Bf[S_REG][8][2];
#pragma unroll
    for (int s = 0; s < S_REG; s++)
#pragma unroll
        for (int nt = 0; nt < 8; nt++)
            ldsm_x2(Bf[s][nt][0], Bf[s][nt][1],
                    (KB0 + (uint32_t)(nt << 11)) ^ (uint32_t)(s << 5));

    const __half2 h2zero = __floats2half2_rn(0.f, 0.f);
    const char* gAc = (const char*)g_Ah;
    const char* gBc = (const char*)g_Bh;

    for (int tile = blockIdx.x; tile < ntiles; tile += gridDim.x) {
        int ebase = tile * TILE_E + warp * WARP_E;

        // Per-lane indices for 32 edges (drug + dis), coalesced.
        int e = ebase + lane;
        int idx_d = 0, idx_s = 0;
        if (e < E) {
            if (is64) {
                idx_d = (int)e64[e];
                idx_s = (int)e64[E + e];
            } else {
                idx_d = e32[e];
                idx_s = e32[E + e];
            }
        }

        // ---- gather: 2 edges/iteration, 16B per lane ----
#pragma unroll
        for (int q2 = 0; q2 < WARP_E; q2 += 2) {
            int qq = q2 + hh;
            int i = __shfl_sync(0xffffffffu, idx_d, qq);
            int j = __shfl_sync(0xffffffffu, idx_s, qq);
            uint4 av = *(const uint4*)(gAc + (((size_t)(uint32_t)i) << 8) + (sl << 4));
            uint4 bv = *(const uint4*)(gBc + (((size_t)(uint32_t)j) << 8) + (sl << 4));
            __half2 r0 = __hmax2(__hadd2(*(__half2*)&av.x, *(__half2*)&bv.x), h2zero);
            __half2 r1 = __hmax2(__hadd2(*(__half2*)&av.y, *(__half2*)&bv.y), h2zero);
            __half2 r2 = __hmax2(__hadd2(*(__half2*)&av.z, *(__half2*)&bv.z), h2zero);
            __half2 r3 = __hmax2(__hadd2(*(__half2*)&av.w, *(__half2*)&bv.w), h2zero);
            uint32_t dst = KSrow + (uint32_t)(q2 << 8)
                         + (KC ^ (uint32_t)((q2 & 7) << 4));
            sts128(dst, *(uint32_t*)&r0, *(uint32_t*)&r1,
                        *(uint32_t*)&r2, *(uint32_t*)&r3);
        }
        __syncwarp();

        // ---- layer 2: 2 x (m16 x n64 x k128) fp16 MMA, fp32 accum ----
        float acc[2][8][4];
#pragma unroll
        for (int m = 0; m < 2; m++)
#pragma unroll
            for (int n = 0; n < 8; n++)
                acc[m][n][0] = acc[m][n][1] = acc[m][n][2] = acc[m][n][3] = 0.f;

#pragma unroll
        for (int s = 0; s < 8; s++) {           // k16 steps
            uint32_t A0[4], A1[4];
            ldsm_x4(A0[0], A0[1], A0[2], A0[3], KA0 ^ (uint32_t)(s << 5));
            ldsm_x4(A1[0], A1[1], A1[2], A1[3], (KA0 + 4096u) ^ (uint32_t)(s << 5));
#pragma unroll
            for (int nt = 0; nt < 8; nt++) {
                uint32_t b0, b1;
                if (s < S_REG) {
                    b0 = Bf[s][nt][0];
                    b1 = Bf[s][nt][1];
                } else {
                    ldsm_x2(b0, b1,
                            (KB0 + (uint32_t)(nt << 11)) ^ (uint32_t)(s << 5));
                }
                mma_fp16(acc[0][nt], A0[0], A0[1], A0[2], A0[3], b0, b1);
                mma_fp16(acc[1][nt], A1[0], A1[1], A1[2], A1[3], b0, b1);
            }
        }

        // ---- epilogue: relu(h2 + b2) . W3 + b3, reduced across the quad ----
#pragma unroll
        for (int m = 0; m < 2; m++) {
            float o0 = 0.f, o1 = 0.f;
#pragma unroll
            for (int n = 0; n < 8; n++) {
                int c0 = n * 8 + 2 * tg;
                float bb0 = b2s[c0], bb1 = b2s[c0 + 1];
                float w0 = w3s[c0],  w1 = w3s[c0 + 1];
                o0 += fmaxf(acc[m][n][0] + bb0, 0.f) * w0
                    + fmaxf(acc[m][n][1] + bb1, 0.f) * w1;
                o1 += fmaxf(acc[m][n][2] + bb0, 0.f) * w0
                    + fmaxf(acc[m][n][3] + bb1, 0.f) * w1;
            }
            o0 += __shfl_xor_sync(0xffffffffu, o0, 1);
            o0 += __shfl_xor_sync(0xffffffffu, o0, 2);
            o1 += __shfl_xor_sync(0xffffffffu, o1, 1);
            o1 += __shfl_xor_sync(0xffffffffu, o1, 2);
            if (tg == 0) {
                int e0 = ebase + m * 16 + g;
                int e1 = e0 + 8;
                if (e0 < E) out[e0] = o0 + b3v;
                if (e1 < E) out[e1] = o1 + b3v;
            }
        }
        __syncwarp();   // next tile's gather rewrites rows this warp just read
    }
}

// ---------------------------------------------------------------------------
// Launch
// ---------------------------------------------------------------------------
extern "C" void kernel_launch(void* const* d_in, const int* in_sizes, int n_in,
                              void* d_out, int out_size) {
    const float* drug = (const float*)d_in[0];
    const float* dis  = (const float*)d_in[1];
    const void*  eraw = d_in[2];
    const float* W1   = (const float*)d_in[3];
    const float* b1   = (const float*)d_in[4];
    const float* W2   = (const float*)d_in[5];
    const float* b2   = (const float*)d_in[6];
    const float* W3   = (const float*)d_in[7];
    const float* b3   = (const float*)d_in[8];
    float* out = (float*)d_out;

    int n_drug  = in_sizes[0] / IN_UNITS;
    int n_dis   = in_sizes[1] / IN_UNITS;
    int n_total = in_sizes[2];       // 2*E elements regardless of dtype
    int E       = n_total / 2;
    int ntiles  = (E + TILE_E - 1) / TILE_E;

    int nblkA = (n_drug + RPB - 1) / RPB;
    int nblkB = (n_dis + RPB - 1) / RPB;
    precompute_AB<<<nblkA + nblkB, IN_UNITS>>>(drug, dis, W1, b1,
                                               n_drug, n_dis, nblkA);

    constexpr int smem_bytes =
        (TILE_E * H1_DIM + H2_DIM * H1_DIM) * 2 + 2 * H2_DIM * 4 + 256;  // ~49 KB
    cudaFuncSetAttribute(edge_mlp_kernel,
                         cudaFuncAttributeMaxDynamicSharedMemorySize,
                         smem_bytes);

    int grid = 444;  // persistent, 3 CTAs/SM (12 warps/SM)
    if (grid > ntiles) grid = ntiles;
    edge_mlp_kernel<<<grid, NTHREADS, smem_bytes>>>(eraw, W2, b2, W3, b3,
                                                    out, E, ntiles);
}

// round 14
// speedup vs baseline: 2.6860x; 1.0130x over previous
#include <cuda_runtime.h>
#include <cuda_fp16.h>
#include <cstdint>

// ---------------------------------------------------------------------------
// MLP over graph edges, factored:
//   h1 = relu(drug[i] @ W1a^T + dis[j] @ W1b^T + b1) = relu(A[i] + B[j])
//   h2 = relu(h1 @ W2^T + b2)       (FP16 tensor-core GEMM, fp32 accum)
//   out = h2 @ W3^T + b3            (register epilogue + quad shuffle reduce)
//
// R13: 16 warps/SM at 1.375 KB L1 bytes/edge — 4 CTAs x 4 warps
// (128-reg ceiling, S_REG=2) + next-tile index prefetch under the MMA phase.
// ---------------------------------------------------------------------------

#define IN_UNITS   128
#define H1_DIM     128
#define H2_DIM     64

#define WARP_E     32                 // edges per warp
#define NWARP      4
#define NTHREADS   (NWARP * 32)
#define TILE_E     (WARP_E * NWARP)   // 128 edges per CTA tile
#define S_REG      2                  // k16 steps whose B-fragments live in regs

#define N_DRUG_MAX 10000
#define N_DIS_MAX  5000

__device__ __align__(16) __half g_Ah[N_DRUG_MAX * H1_DIM];
__device__ __align__(16) __half g_Bh[N_DIS_MAX * H1_DIM];

__device__ __forceinline__ uint32_t smem_u32(const void* p) {
    return (uint32_t)__cvta_generic_to_shared(p);
}

__device__ __forceinline__ void ldsm_x4(uint32_t& r0, uint32_t& r1,
                                        uint32_t& r2, uint32_t& r3,
                                        uint32_t addr) {
    asm volatile("ldmatrix.sync.aligned.m8n8.x4.shared.b16 {%0,%1,%2,%3}, [%4];"
                 : "=r"(r0), "=r"(r1), "=r"(r2), "=r"(r3) : "r"(addr));
}
__device__ __forceinline__ void ldsm_x2(uint32_t& r0, uint32_t& r1,
                                        uint32_t addr) {
    asm volatile("ldmatrix.sync.aligned.m8n8.x2.shared.b16 {%0,%1}, [%2];"
                 : "=r"(r0), "=r"(r1) : "r"(addr));
}
__device__ __forceinline__ void sts128(uint32_t addr, uint32_t r0, uint32_t r1,
                                       uint32_t r2, uint32_t r3) {
    asm volatile("st.shared.v4.b32 [%0], {%1,%2,%3,%4};"
                 :: "r"(addr), "r"(r0), "r"(r1), "r"(r2), "r"(r3) : "memory");
}
__device__ __forceinline__ void mma_fp16(float acc[4],
        uint32_t a0, uint32_t a1, uint32_t a2, uint32_t a3,
        uint32_t b0, uint32_t b1) {
    asm volatile(
        "mma.sync.aligned.m16n8k16.row.col.f32.f16.f16.f32 "
        "{%0,%1,%2,%3}, {%4,%5,%6,%7}, {%8,%9}, {%0,%1,%2,%3};\n"
        : "+f"(acc[0]), "+f"(acc[1]), "+f"(acc[2]), "+f"(acc[3])
        : "r"(a0), "r"(a1), "r"(a2), "r"(a3), "r"(b0), "r"(b1));
}

// ---------------------------------------------------------------------------
// Precompute (fp32 math, fp16 store), 32 rows/block, A and B in ONE launch:
//   blocks [0, nblkA)      : A[row] = drug_feat[row] @ W1[:, 0:128]^T
//   blocks [nblkA, total)  : B[row] = dis_feat[row]  @ W1[:, 128:256]^T + b1
// ---------------------------------------------------------------------------
#define RPB 32

__global__ void precompute_AB(const float* __restrict__ drug,
                              const float* __restrict__ dis,
                              const float* __restrict__ W1,
                              const float* __restrict__ b1,
                              int n_drug, int n_dis, int nblkA) {
    bool isA = (int)blockIdx.x < nblkA;
    const float* feat = isA ? drug : dis;
    int nrows  = isA ? n_drug : n_dis;
    int row0   = (isA ? blockIdx.x : blockIdx.x - nblkA) * RPB;
    int c = threadIdx.x;

    __shared__ float sf[RPB][IN_UNITS];
    for (int r = 0; r < RPB; r++) {
        int row = row0 + r;
        sf[r][c] = (row < nrows) ? feat[row * IN_UNITS + c] : 0.f;
    }
    __syncthreads();

    float init = isA ? 0.f : b1[c];
    float acc[RPB];
#pragma unroll
    for (int r = 0; r < RPB; r++) acc[r] = init;

    const float4* w = (const float4*)(W1 + c * (2 * IN_UNITS) + (isA ? 0 : IN_UNITS));
#pragma unroll 4
    for (int k = 0; k < IN_UNITS / 4; k++) {
        float4 ww = w[k];
#pragma unroll
        for (int r = 0; r < RPB; r++) {
            float4 f = *(const float4*)&sf[r][k * 4];
            acc[r] += f.x * ww.x + f.y * ww.y + f.z * ww.z + f.w * ww.w;
        }
    }
    __half* dst = isA ? g_Ah : g_Bh;
    for (int r = 0; r < RPB; r++) {
        int row = row0 + r;
        if (row < nrows) dst[row * H1_DIM + c] = __float2half_rn(acc[r]);
    }
}

// ---------------------------------------------------------------------------
// Main fused kernel. SMEM (fp16, XOR-swizzled, 16B chunk granularity):
//   H1h:  TILE_E rows x 256B (16 chunks/row; phys chunk = c ^ (row&7))
//   W2h:  64 rows x 256B, same swizzle
// B-fragments: s<S_REG register-resident, rest ldsm'd per tile.
// Next tile's edge indices prefetched before the MMA phase.
// ---------------------------------------------------------------------------
__global__ __launch_bounds__(NTHREADS, 4)
void edge_mlp_kernel(const void* __restrict__ eraw,
                     const float* __restrict__ W2,
                     const float* __restrict__ b2,
                     const float* __restrict__ W3,
                     const float* __restrict__ b3,
                     float* __restrict__ out,
                     int E, int ntiles) {
    extern __shared__ char smraw[];
    // 256B-align the working base so the chunk field (bits 4..7) is pure.
    uint32_t s0 = smem_u32(smraw);
    uint32_t padb = ((s0 + 255u) & ~255u) - s0;
    char* smbase = smraw + padb;
    __half* H1h = (__half*)smbase;                 // TILE_E * 128 halves
    __half* W2h = H1h + TILE_E * H1_DIM;           // 64 * 128 halves
    float*  b2s = (float*)(W2h + H2_DIM * H1_DIM); // 64
    float*  w3s = b2s + H2_DIM;                    // 64
    __shared__ int s_is64;

    int tid = threadIdx.x;

    // Detect index dtype once per CTA (int64 values < 5000 -> hi words 0).
    if (tid == 0) {
        const unsigned long long* r64 = (const unsigned long long*)eraw;
        int is64 = 1;
        #pragma unroll 8
        for (int k = 0; k < 64; k++)
            if (r64[k] >> 32) { is64 = 0; break; }
        s_is64 = is64;
    }

    // Stage W2 (fp16, swizzled), b2, W3 once per CTA.
    for (int t = tid; t < H2_DIM * H1_DIM; t += NTHREADS) {
        int n = t >> 7, k = t & 127;
        int phys = n * H1_DIM + (((k >> 3) ^ (n & 7)) << 3) + (k & 7);
        W2h[phys] = __float2half_rn(W2[t]);
    }
    if (tid < H2_DIM) { b2s[tid] = b2[tid]; w3s[tid] = W3[tid]; }
    __syncthreads();
    float b3v = __ldg(b3);
    bool is64 = (s_is64 != 0);
    const long long* e64 = (const long long*)eraw;
    const int*       e32 = (const int*)eraw;

    int warp = tid >> 5;
    int lane = tid & 31;
    int g  = lane >> 2;   // mma groupID
    int tg = lane & 3;    // mma thread-in-group
    uint32_t hw_u32 = smem_u32(H1h) + warp * (WARP_E * 256);  // 8KB/warp
    uint32_t w2_u32 = smem_u32(W2h);

    // ---- address constants ----
    int sl = lane & 15;
    int hh = lane >> 4;
    uint32_t KSrow = hw_u32 + ((uint32_t)hh << 8);
    uint32_t KC    = (uint32_t)((sl ^ hh) << 4);
    int ar = lane & 15;
    int ac_hi = lane >> 4;
    uint32_t KA0 = hw_u32 + (ar << 8) + ((((ar & 7) ^ ac_hi)) << 4);
    int bn = lane & 7;
    int bc_hi = (lane >> 3) & 1;
    uint32_t KB0 = w2_u32 + (bn << 8) + (((bn ^ bc_hi)) << 4);

    // ---- preload B-fragments for k-steps 0..S_REG-1 (tile-invariant) ----
    uint32_t Bf[S_REG][8][2];
#pragma unroll
    for (int s = 0; s < S_REG; s++)
#pragma unroll
        for (int nt = 0; nt < 8; nt++)
            ldsm_x2(Bf[s][nt][0], Bf[s][nt][1],
                    (KB0 + (uint32_t)(nt << 11)) ^ (uint32_t)(s << 5));

    const __half2 h2zero = __floats2half2_rn(0.f, 0.f);
    const char* gAc = (const char*)g_Ah;
    const char* gBc = (const char*)g_Bh;

    // ---- index load helper (per-lane, 32 edges per warp) ----
    auto load_idx = [&](int tile, int& idx_d, int& idx_s) {
        int e = tile * TILE_E + warp * WARP_E + lane;
        idx_d = 0; idx_s = 0;
        if (tile < ntiles && e < E) {
            if (is64) { idx_d = (int)e64[e]; idx_s = (int)e64[E + e]; }
            else      { idx_d = e32[e];      idx_s = e32[E + e]; }
        }
    };

    int idx_d, idx_s;
    load_idx(blockIdx.x, idx_d, idx_s);

    for (int tile = blockIdx.x; tile < ntiles; tile += gridDim.x) {
        int ebase = tile * TILE_E + warp * WARP_E;

        // ---- gather: 2 edges/iteration, 16B per lane ----
#pragma unroll
        for (int q2 = 0; q2 < WARP_E; q2 += 2) {
            int qq = q2 + hh;
            int i = __shfl_sync(0xffffffffu, idx_d, qq);
            int j = __shfl_sync(0xffffffffu, idx_s, qq);
            uint4 av = *(const uint4*)(gAc + (((size_t)(uint32_t)i) << 8) + (sl << 4));
            uint4 bv = *(const uint4*)(gBc + (((size_t)(uint32_t)j) << 8) + (sl << 4));
            __half2 r0 = __hmax2(__hadd2(*(__half2*)&av.x, *(__half2*)&bv.x), h2zero);
            __half2 r1 = __hmax2(__hadd2(*(__half2*)&av.y, *(__half2*)&bv.y), h2zero);
            __half2 r2 = __hmax2(__hadd2(*(__half2*)&av.z, *(__half2*)&bv.z), h2zero);
            __half2 r3 = __hmax2(__hadd2(*(__half2*)&av.w, *(__half2*)&bv.w), h2zero);
            uint32_t dst = KSrow + (uint32_t)(q2 << 8)
                         + (KC ^ (uint32_t)((q2 & 7) << 4));
            sts128(dst, *(uint32_t*)&r0, *(uint32_t*)&r1,
                        *(uint32_t*)&r2, *(uint32_t*)&r3);
        }
        __syncwarp();

        // ---- prefetch next tile's indices (latency hidden under MMA) ----
        int nidx_d, nidx_s;
        load_idx(tile + gridDim.x, nidx_d, nidx_s);

        // ---- layer 2: 2 x (m16 x n64 x k128) fp16 MMA, fp32 accum ----
        float acc[2][8][4];
#pragma unroll
        for (int m = 0; m < 2; m++)
#pragma unroll
            for (int n = 0; n < 8; n++)
                acc[m][n][0] = acc[m][n][1] = acc[m][n][2] = acc[m][n][3] = 0.f;

#pragma unroll
        for (int s = 0; s < 8; s++) {           // k16 steps
            uint32_t A0[4], A1[4];
            ldsm_x4(A0[0], A0[1], A0[2], A0[3], KA0 ^ (uint32_t)(s << 5));
            ldsm_x4(A1[0], A1[1], A1[2], A1[3], (KA0 + 4096u) ^ (uint32_t)(s << 5));
#pragma unroll
            for (int nt = 0; nt < 8; nt++) {
                uint32_t b0, b1;
                if (s < S_REG) {
                    b0 = Bf[s][nt][0];
                    b1 = Bf[s][nt][1];
                } else {
                    ldsm_x2(b0, b1,
                            (KB0 + (uint32_t)(nt << 11)) ^ (uint32_t)(s << 5));
                }
                mma_fp16(acc[0][nt], A0[0], A0[1], A0[2], A0[3], b0, b1);
                mma_fp16(acc[1][nt], A1[0], A1[1], A1[2], A1[3], b0, b1);
            }
        }

        // ---- epilogue: relu(h2 + b2) . W3 + b3, reduced across the quad ----
#pragma unroll
        for (int m = 0; m < 2; m++) {
            float o0 = 0.f, o1 = 0.f;
#pragma unroll
            for (int n = 0; n < 8; n++) {
                int c0 = n * 8 + 2 * tg;
                float bb0 = b2s[c0], bb1 = b2s[c0 + 1];
                float w0 = w3s[c0],  w1 = w3s[c0 + 1];
                o0 += fmaxf(acc[m][n][0] + bb0, 0.f) * w0
                    + fmaxf(acc[m][n][1] + bb1, 0.f) * w1;
                o1 += fmaxf(acc[m][n][2] + bb0, 0.f) * w0
                    + fmaxf(acc[m][n][3] + bb1, 0.f) * w1;
            }
            o0 += __shfl_xor_sync(0xffffffffu, o0, 1);
            o0 += __shfl_xor_sync(0xffffffffu, o0, 2);
            o1 += __shfl_xor_sync(0xffffffffu, o1, 1);
            o1 += __shfl_xor_sync(0xffffffffu, o1, 2);
            if (tg == 0) {
                int e0 = ebase + m * 16 + g;
                int e1 = e0 + 8;
                if (e0 < E) out[e0] = o0 + b3v;
                if (e1 < E) out[e1] = o1 + b3v;
            }
        }
        idx_d = nidx_d;
        idx_s = nidx_s;
        __syncwarp();   // next tile's gather rewrites rows this warp just read
    }
}

// ---------------------------------------------------------------------------
// Launch
// ---------------------------------------------------------------------------
extern "C" void kernel_launch(void* const* d_in, const int* in_sizes, int n_in,
                              void* d_out, int out_size) {
    const float* drug = (const float*)d_in[0];
    const float* dis  = (const float*)d_in[1];
    const void*  eraw = d_in[2];
    const float* W1   = (const float*)d_in[3];
    const float* b1   = (const float*)d_in[4];
    const float* W2   = (const float*)d_in[5];
    const float* b2   = (const float*)d_in[6];
    const float* W3   = (const float*)d_in[7];
    const float* b3   = (const float*)d_in[8];
    float* out = (float*)d_out;

    int n_drug  = in_sizes[0] / IN_UNITS;
    int n_dis   = in_sizes[1] / IN_UNITS;
    int n_total = in_sizes[2];       // 2*E elements regardless of dtype
    int E       = n_total / 2;
    int ntiles  = (E + TILE_E - 1) / TILE_E;

    int nblkA = (n_drug + RPB - 1) / RPB;
    int nblkB = (n_dis + RPB - 1) / RPB;
    precompute_AB<<<nblkA + nblkB, IN_UNITS>>>(drug, dis, W1, b1,
                                               n_drug, n_dis, nblkA);

    constexpr int smem_bytes =
        (TILE_E * H1_DIM + H2_DIM * H1_DIM) * 2 + 2 * H2_DIM * 4 + 256;  // ~49 KB
    cudaFuncSetAttribute(edge_mlp_kernel,
                         cudaFuncAttributeMaxDynamicSharedMemorySize,
                         smem_bytes);

    int grid = 592;  // persistent, 4 CTAs/SM (16 warps/SM)
    if (grid > ntiles) grid = ntiles;
    edge_mlp_kernel<<<grid, NTHREADS, smem_bytes>>>(eraw, W2, b2, W3, b3,
                                                    out, E, ntiles);
}